// round 3
// baseline (speedup 1.0000x reference)
#include <cuda_runtime.h>
#include <math.h>

#define P      512
#define K_MAX  16
#define KC     32
#define M_CAP  65536
#define NB2    64
#define PPAD   452   // panel row pitch (>= 448, mult of 4, odd/32 for banks)

// dynamic smem floats for k_chol: diag 64x65, dinv 64, panel 64x452
#define CHOL_SMEM_FLOATS (NB2*65 + NB2 + NB2*PPAD)
#define CHOL_SMEM_BYTES  (CHOL_SMEM_FLOATS * 4)

// ---------------- device scratch (static: no allocations allowed) ----------
__device__ int   d_cnt[K_MAX];
__device__ int   d_kval;
__device__ int   d_is64;
__device__ int   d_cls[M_CAP];
__device__ float d_Gk[K_MAX][P][P];
__device__ float d_A[K_MAX + 1][P * P];
__device__ float d_hld[K_MAX + 1];

// ------- init: zero counts, read num_classes, detect Y dtype (i32 vs i64) --
__global__ void k_init(const int* ncls, const int* yw) {
    __shared__ int nz;
    int t = threadIdx.x;
    if (t == 0) nz = 0;
    __syncthreads();
    int found = 0;
    for (int i = t; i < 512; i += blockDim.x)
        if (yw[2 * i + 1] != 0) found = 1;
    if (__any_sync(0xffffffffu, found)) {
        if ((t & 31) == 0) atomicOr(&nz, 1);
    }
    __syncthreads();
    if (t < K_MAX) d_cnt[t] = 0;
    if (t == 0) {
        d_is64 = nz ? 0 : 1;
        int k = ncls ? *ncls : 10;
        if (k < 1) k = 1;
        if (k > K_MAX) k = K_MAX;
        d_kval = k;
    }
}

// ---------------- prep: labels -> int32 array, class histogram --------------
__global__ void k_prep(const void* __restrict__ Y, int m) {
    int i = blockIdx.x * blockDim.x + threadIdx.x;
    if (i >= m || i >= M_CAP) return;
    int cv = d_is64 ? (int)((const long long*)Y)[i] : ((const int*)Y)[i];
    d_cls[i] = cv;
    if (cv >= 0 && cv < K_MAX) atomicAdd(&d_cnt[cv], 1);
}

// ---------------- per-class Gram: Gk[c] = sum_{i: y_i=c} x_i x_i^T ---------
__global__ __launch_bounds__(256) void k_gram(const float* __restrict__ X,
                                              int m, int p) {
    int c = blockIdx.y;
    if (c >= d_kval) return;
    int tile = blockIdx.x;                  // lower-triangular 128-tile index
    int ti = 0;
    while ((ti + 1) * (ti + 2) / 2 <= tile) ti++;
    int tj = tile - ti * (ti + 1) / 2;
    int a0 = ti * 128, b0 = tj * 128;

    __shared__ __align__(16) float sA[KC][132];
    __shared__ __align__(16) float sB[KC][132];
    __shared__ int scls[KC];

    int tid = threadIdx.x;
    int tx = tid & 15, ty = tid >> 4;       // 16x16 thread grid
    int lt = tid >> 3, lc = tid & 7;        // load mapping: row t, col group

    float acc[8][8];
#pragma unroll
    for (int i = 0; i < 8; i++)
#pragma unroll
        for (int j = 0; j < 8; j++) acc[i][j] = 0.f;

    for (int base = 0; base < m; base += KC) {
        if (tid < KC) {
            int s = base + tid;
            scls[tid] = (s < m) ? d_cls[s] : -1;
        }
        __syncthreads();

        {
            int s = base + lt;
            if (scls[lt] == c) {
                const float* xr = X + (size_t)s * p;
#pragma unroll
                for (int q = 0; q < 4; q++) {
                    int col = lc * 16 + q * 4;
                    *(float4*)&sA[lt][col] = *(const float4*)&xr[a0 + col];
                    *(float4*)&sB[lt][col] = *(const float4*)&xr[b0 + col];
                }
            }
        }
        __syncthreads();

#pragma unroll 8
        for (int t = 0; t < KC; t++) {
            if (scls[t] != c) continue;     // warp-uniform skip
            float a[8], b[8];
            *(float4*)&a[0] = *(const float4*)&sA[t][ty * 8];
            *(float4*)&a[4] = *(const float4*)&sA[t][ty * 8 + 4];
            *(float4*)&b[0] = *(const float4*)&sB[t][tx * 8];
            *(float4*)&b[4] = *(const float4*)&sB[t][tx * 8 + 4];
#pragma unroll
            for (int ii = 0; ii < 8; ii++)
#pragma unroll
                for (int jj = 0; jj < 8; jj++)
                    acc[ii][jj] = fmaf(a[ii], b[jj], acc[ii][jj]);
        }
        __syncthreads();
    }

    float* G = &d_Gk[c][0][0];
    int gi = a0 + ty * 8, gj = b0 + tx * 8;
#pragma unroll
    for (int ii = 0; ii < 8; ii++) {
        *(float4*)&G[(size_t)(gi + ii) * P + gj]     = *(float4*)&acc[ii][0];
        *(float4*)&G[(size_t)(gi + ii) * P + gj + 4] = *(float4*)&acc[ii][4];
    }
    if (ti != tj) {                          // mirror to upper triangle
#pragma unroll
        for (int ii = 0; ii < 8; ii++)
#pragma unroll
            for (int jj = 0; jj < 8; jj++)
                G[(size_t)(gj + jj) * P + gi + ii] = acc[ii][jj];
    }
}

// ---------------- assemble A_j = I + scal_j*Gk_j, A_k = I + scalar*G -------
__global__ void k_assemble(int m, float pf) {
    int idx = blockIdx.x * blockDim.x + threadIdx.x;
    if (idx >= P * P) return;
    int r = idx >> 9, cc = idx & 511;
    int kv = d_kval;
    float diag = (r == cc) ? 1.f : 0.f;
    float sum = 0.f;
    for (int j = 0; j < kv; j++) {
        float g = d_Gk[j][r][cc];
        sum += g;
        float trPi = (float)d_cnt[j] + 1e-8f;
        float scal = pf / (trPi * 0.01f);
        d_A[j][idx] = diag + scal * g;
    }
    float scalar = pf / ((float)m * 0.01f);
    d_A[kv][idx] = diag + scalar * sum;
}

// ---------------- blocked Cholesky logdet, NB=64, one CTA per matrix -------
__global__ __launch_bounds__(256) void k_chol() {
    int mb = blockIdx.x;
    if (mb > d_kval) return;
    float* A = d_A[mb];

    extern __shared__ float sm[];
    float* sD    = sm;                    // [64][65]
    float* sdinv = sm + NB2 * 65;         // [64]
    float* sP    = sdinv + NB2;           // [64][PPAD]
    __shared__ double sLog;

    int tid = threadIdx.x;
    if (tid == 0) sLog = 0.0;

    for (int s = 0; s < P / NB2; s++) {
        int sc = s * NB2;

        // ---- load 64x64 diagonal block ----
        for (int l = tid; l < NB2 * NB2; l += 256) {
            int r = l >> 6, c = l & 63;
            sD[r * 65 + c] = A[(size_t)(sc + r) * P + sc + c];
        }
        __syncthreads();

        // ---- factor diag block in smem (256-thread right-looking) ----
        for (int t = 0; t < NB2; t++) {
            if (tid == 0) {
                float dv = sqrtf(sD[t * 65 + t]);
                sD[t * 65 + t] = dv;
                sdinv[t] = 1.f / dv;
            }
            __syncthreads();
            float dinv = sdinv[t];
            for (int i = t + 1 + tid; i < NB2; i += 256)
                sD[i * 65 + t] *= dinv;
            __syncthreads();
            for (int l = (t + 1) * 64 + tid; l < NB2 * NB2; l += 256) {
                int i = l >> 6, u = l & 63;
                if (u > t && i >= u)
                    sD[i * 65 + u] = fmaf(-sD[i * 65 + t], sD[u * 65 + t],
                                          sD[i * 65 + u]);
            }
            __syncthreads();
        }
        if (tid == 0) {
            double lsum = 0.0;
            for (int t = 0; t < NB2; t++)
                lsum += (double)logf(sD[t * 65 + t]);
            sLog += lsum;
        }
        __syncthreads();

        int rem = P - sc - NB2;
        if (rem > 0) {
            // ---- panel solve: x = A_row * L^-T, deposit into sP[t][row] ----
            for (int rr = tid; rr < rem; rr += 256) {
                const float* Ar = &A[(size_t)(sc + NB2 + rr) * P + sc];
                float x[NB2];
#pragma unroll
                for (int q = 0; q < NB2 / 4; q++)
                    *(float4*)&x[q * 4] = *(const float4*)&Ar[q * 4];
#pragma unroll
                for (int t = 0; t < NB2; t++) {
                    x[t] *= sdinv[t];
                    float xt = x[t];
#pragma unroll
                    for (int u = t + 1; u < NB2; u++)
                        x[u] = fmaf(-xt, sD[u * 65 + t], x[u]);
                }
#pragma unroll
                for (int t = 0; t < NB2; t++)
                    sP[t * PPAD + rr] = x[t];
            }
            __syncthreads();

            // ---- trailing update: A -= P^T P, lower 8x8 tiles ----
            int rem8 = rem >> 3;
            int ntile = rem8 * (rem8 + 1) / 2;
            for (int l = tid; l < ntile; l += 256) {
                int ti = (int)((sqrtf(8.f * (float)l + 1.f) - 1.f) * 0.5f);
                while ((ti + 1) * (ti + 2) / 2 <= l) ti++;
                while (ti * (ti + 1) / 2 > l) ti--;
                int tj = l - ti * (ti + 1) / 2;
                int i0 = ti * 8, j0 = tj * 8;

                float acc[8][8];
#pragma unroll
                for (int ii = 0; ii < 8; ii++)
#pragma unroll
                    for (int jj = 0; jj < 8; jj++) acc[ii][jj] = 0.f;

#pragma unroll 16
                for (int t = 0; t < NB2; t++) {
                    float a[8], b[8];
                    *(float4*)&a[0] = *(const float4*)&sP[t * PPAD + i0];
                    *(float4*)&a[4] = *(const float4*)&sP[t * PPAD + i0 + 4];
                    *(float4*)&b[0] = *(const float4*)&sP[t * PPAD + j0];
                    *(float4*)&b[4] = *(const float4*)&sP[t * PPAD + j0 + 4];
#pragma unroll
                    for (int ii = 0; ii < 8; ii++)
#pragma unroll
                        for (int jj = 0; jj < 8; jj++)
                            acc[ii][jj] = fmaf(a[ii], b[jj], acc[ii][jj]);
                }

                int gr = sc + NB2 + i0, gc = sc + NB2 + j0;
#pragma unroll
                for (int ii = 0; ii < 8; ii++) {
                    float* row = &A[(size_t)(gr + ii) * P + gc];
                    float4 v0 = *(float4*)&row[0];
                    float4 v1 = *(float4*)&row[4];
                    v0.x -= acc[ii][0]; v0.y -= acc[ii][1];
                    v0.z -= acc[ii][2]; v0.w -= acc[ii][3];
                    v1.x -= acc[ii][4]; v1.y -= acc[ii][5];
                    v1.z -= acc[ii][6]; v1.w -= acc[ii][7];
                    *(float4*)&row[0] = v0;
                    *(float4*)&row[4] = v1;
                }
            }
        }
        __syncthreads();
    }

    if (tid == 0) d_hld[mb] = (float)sLog;   // half-logdet = sum log(L_ii)
}

// ---------------- finalize: two scalars ------------------------------------
__global__ void k_final(float* out, int m) {
    if (threadIdx.x != 0) return;
    int kv = d_kval;
    float comp = 0.f;
    for (int j = 0; j < kv; j++) {
        float trPi = (float)d_cnt[j] + 1e-8f;
        comp += d_hld[j] * trPi / (float)m;
    }
    out[0] = d_hld[kv];
    out[1] = comp;
}

// ---------------- launch ----------------------------------------------------
extern "C" void kernel_launch(void* const* d_in, const int* in_sizes, int n_in,
                              void* d_out, int out_size) {
    const float* X    = (const float*)d_in[0];
    const void*  Y    = d_in[1];
    const int*   ncls = (n_in >= 3) ? (const int*)d_in[2] : nullptr;
    int m = in_sizes[1];
    int p = in_sizes[0] / m;          // 512
    float* out = (float*)d_out;
    (void)out_size;

    cudaFuncSetAttribute(k_chol, cudaFuncAttributeMaxDynamicSharedMemorySize,
                         CHOL_SMEM_BYTES);

    k_init<<<1, 256>>>(ncls, (const int*)Y);
    k_prep<<<(m + 255) / 256, 256>>>(Y, m);
    k_gram<<<dim3(10, K_MAX), 256>>>(X, m, p);
    k_assemble<<<(P * P + 255) / 256, 256>>>(m, (float)p);
    k_chol<<<K_MAX + 1, 256, CHOL_SMEM_BYTES>>>();
    k_final<<<1, 32>>>(out, m);
}

// round 4
// speedup vs baseline: 1.9277x; 1.9277x over previous
#include <cuda_runtime.h>
#include <math.h>

#define P       512
#define K_MAX   16
#define NM      (K_MAX + 1)
#define KC      32
#define M_CAP   65536
#define NB      64
#define NSTEP   (P / NB)      // 8
#define NSLICE  3

// ---------------- device scratch (static: no allocations allowed) ----------
__device__ int    d_cnt[K_MAX];
__device__ int    d_kval;
__device__ int    d_is64;
__device__ int    d_cls[M_CAP];
__device__ float  d_Gk[NSLICE][K_MAX][P * P];
__device__ float  d_A[NM][P * P];
__device__ float  d_invL[NM][NB * 65];
__device__ double d_hldd[NM];

// ------- init: zero counts/hld, read num_classes, detect Y dtype -----------
__global__ void k_init(const int* ncls, const int* yw) {
    __shared__ int nz;
    int t = threadIdx.x;
    if (t == 0) nz = 0;
    __syncthreads();
    int found = 0;
    for (int i = t; i < 512; i += blockDim.x)
        if (yw[2 * i + 1] != 0) found = 1;
    if (__any_sync(0xffffffffu, found)) {
        if ((t & 31) == 0) atomicOr(&nz, 1);
    }
    __syncthreads();
    if (t < K_MAX) d_cnt[t] = 0;
    if (t < NM) d_hldd[t] = 0.0;
    if (t == 0) {
        d_is64 = nz ? 0 : 1;
        int k = ncls ? *ncls : 10;
        if (k < 1) k = 1;
        if (k > K_MAX) k = K_MAX;
        d_kval = k;
    }
}

// ---------------- prep: labels -> int32 array, class histogram --------------
__global__ void k_prep(const void* __restrict__ Y, int m) {
    int i = blockIdx.x * blockDim.x + threadIdx.x;
    if (i >= m || i >= M_CAP) return;
    int cv = d_is64 ? (int)((const long long*)Y)[i] : ((const int*)Y)[i];
    d_cls[i] = cv;
    if (cv >= 0 && cv < K_MAX) atomicAdd(&d_cnt[cv], 1);
}

// ---------------- per-class Gram (m-sliced): Gk[z][c] partial sums ---------
__global__ __launch_bounds__(256) void k_gram(const float* __restrict__ X,
                                              int m, int p) {
    int c = blockIdx.y;
    if (c >= d_kval) return;
    int tile = blockIdx.x;                  // lower-triangular 128-tile index
    int ti = 0;
    while ((ti + 1) * (ti + 2) / 2 <= tile) ti++;
    int tj = tile - ti * (ti + 1) / 2;
    int a0 = ti * 128, b0 = tj * 128;
    int z = blockIdx.z;
    int sb = (int)((long long)m * z / NSLICE) / KC * KC;
    int se = (z == NSLICE - 1) ? m
             : (int)((long long)m * (z + 1) / NSLICE) / KC * KC;

    __shared__ __align__(16) float sA[KC][132];
    __shared__ __align__(16) float sB[KC][132];
    __shared__ int scls[KC];

    int tid = threadIdx.x;
    int tx = tid & 15, ty = tid >> 4;
    int lt = tid >> 3, lc = tid & 7;

    float acc[8][8];
#pragma unroll
    for (int i = 0; i < 8; i++)
#pragma unroll
        for (int j = 0; j < 8; j++) acc[i][j] = 0.f;

    for (int base = sb; base < se; base += KC) {
        if (tid < KC) {
            int s = base + tid;
            scls[tid] = (s < m) ? d_cls[s] : -1;
        }
        __syncthreads();
        {
            int s = base + lt;
            if (scls[lt] == c) {
                const float* xr = X + (size_t)s * p;
#pragma unroll
                for (int q = 0; q < 4; q++) {
                    int col = lc * 16 + q * 4;
                    *(float4*)&sA[lt][col] = *(const float4*)&xr[a0 + col];
                    *(float4*)&sB[lt][col] = *(const float4*)&xr[b0 + col];
                }
            }
        }
        __syncthreads();

#pragma unroll 8
        for (int t = 0; t < KC; t++) {
            if (scls[t] != c) continue;     // warp-uniform skip
            float a[8], b[8];
            *(float4*)&a[0] = *(const float4*)&sA[t][ty * 8];
            *(float4*)&a[4] = *(const float4*)&sA[t][ty * 8 + 4];
            *(float4*)&b[0] = *(const float4*)&sB[t][tx * 8];
            *(float4*)&b[4] = *(const float4*)&sB[t][tx * 8 + 4];
#pragma unroll
            for (int ii = 0; ii < 8; ii++)
#pragma unroll
                for (int jj = 0; jj < 8; jj++)
                    acc[ii][jj] = fmaf(a[ii], b[jj], acc[ii][jj]);
        }
        __syncthreads();
    }

    float* G = d_Gk[z][c];
    int gi = a0 + ty * 8, gj = b0 + tx * 8;
#pragma unroll
    for (int ii = 0; ii < 8; ii++) {
        *(float4*)&G[(size_t)(gi + ii) * P + gj]     = *(float4*)&acc[ii][0];
        *(float4*)&G[(size_t)(gi + ii) * P + gj + 4] = *(float4*)&acc[ii][4];
    }
    if (ti != tj) {
#pragma unroll
        for (int ii = 0; ii < 8; ii++)
#pragma unroll
            for (int jj = 0; jj < 8; jj++)
                G[(size_t)(gj + jj) * P + gi + ii] = acc[ii][jj];
    }
}

// --------- assemble A_j = I + scal_j*(sum slices), A_kv = I + scalar*G -----
__global__ __launch_bounds__(256) void k_assemble(int m, float pf) {
    int idx4 = blockIdx.x * blockDim.x + threadIdx.x;
    if (idx4 >= P * P / 4) return;
    int idx = idx4 * 4;
    int r = idx >> 9, c0 = idx & 511;
    int kv = d_kval;
    float dg[4];
#pragma unroll
    for (int q = 0; q < 4; q++) dg[q] = (r == c0 + q) ? 1.f : 0.f;
    float sum[4] = {0.f, 0.f, 0.f, 0.f};
    for (int j = 0; j < kv; j++) {
        float4 g0 = *(const float4*)&d_Gk[0][j][idx];
        float4 g1 = *(const float4*)&d_Gk[1][j][idx];
        float4 g2 = *(const float4*)&d_Gk[2][j][idx];
        float g[4];
        g[0] = g0.x + g1.x + g2.x; g[1] = g0.y + g1.y + g2.y;
        g[2] = g0.z + g1.z + g2.z; g[3] = g0.w + g1.w + g2.w;
        float scal = pf / (((float)d_cnt[j] + 1e-8f) * 0.01f);
        float4 o;
        o.x = dg[0] + scal * g[0]; o.y = dg[1] + scal * g[1];
        o.z = dg[2] + scal * g[2]; o.w = dg[3] + scal * g[3];
        *(float4*)&d_A[j][idx] = o;
#pragma unroll
        for (int q = 0; q < 4; q++) sum[q] += g[q];
    }
    float scalar = pf / ((float)m * 0.01f);
    float4 o;
    o.x = dg[0] + scalar * sum[0]; o.y = dg[1] + scalar * sum[1];
    o.z = dg[2] + scalar * sum[2]; o.w = dg[3] + scalar * sum[3];
    *(float4*)&d_A[kv][idx] = o;
}

// ---- k_diag: factor 64x64 diag block in smem, logdet, blocked invL --------
__global__ __launch_bounds__(256) void k_diag(int s) {
    int mb = blockIdx.x;
    if (mb > d_kval) return;
    float* A = d_A[mb];
    int sc = s * NB;

    __shared__ float sD[NB * 65];
    __shared__ float sI[NB * 65];
    __shared__ float sM[32 * 33];
    __shared__ float sdinv[NB];
    __shared__ float sRed[NB];
    int tid = threadIdx.x;

    for (int l = tid; l < NB * NB; l += 256) {
        int r = l >> 6, c = l & 63;
        sD[r * 65 + c] = A[(size_t)(sc + r) * P + sc + c];
    }
    for (int l = tid; l < NB * 65; l += 256) sI[l] = 0.f;
    __syncthreads();

    // right-looking Cholesky of the 64x64 block (lower triangle)
    for (int t = 0; t < NB; t++) {
        if (tid == 0) {
            float dv = sqrtf(sD[t * 65 + t]);
            sD[t * 65 + t] = dv;
            sdinv[t] = 1.f / dv;
        }
        __syncthreads();
        float dinv = sdinv[t];
        for (int i = t + 1 + tid; i < NB; i += 256)
            sD[i * 65 + t] *= dinv;
        __syncthreads();
        int u = t + 1 + (tid >> 2);
        if (u < NB) {
            float lut = sD[u * 65 + t];
            for (int i = u + (tid & 3); i < NB; i += 4)
                sD[i * 65 + u] = fmaf(-sD[i * 65 + t], lut, sD[i * 65 + u]);
        }
        __syncthreads();
    }

    if (tid < NB) sRed[tid] = logf(sD[tid * 65 + tid]);
    __syncthreads();
    if (tid == 0) {
        double acc = 0.0;
        for (int t = 0; t < NB; t++) acc += (double)sRed[t];
        d_hldd[mb] += acc;
    }

    // blocked triangular inverse: inv11/inv22 (32x32) then off-diag block
    if (tid < 64) {
        int half = tid >> 5, c = tid & 31, b = half * 32;
        for (int i = c; i < 32; i++) {
            float acc = (i == c) ? 1.f : 0.f;
            for (int u = c; u < i; u++)
                acc = fmaf(-sD[(b + i) * 65 + b + u], sI[(b + u) * 65 + b + c],
                           acc);
            sI[(b + i) * 65 + b + c] = acc * sdinv[b + i];
        }
    }
    __syncthreads();
    // M = L21 * inv11
    for (int l = tid; l < 32 * 32; l += 256) {
        int i = l >> 5, j = l & 31;
        float acc = 0.f;
        for (int u = j; u < 32; u++)
            acc = fmaf(sD[(32 + i) * 65 + u], sI[u * 65 + j], acc);
        sM[i * 33 + j] = acc;
    }
    __syncthreads();
    // off-diag of invL = -inv22 * M
    for (int l = tid; l < 32 * 32; l += 256) {
        int i = l >> 5, j = l & 31;
        float acc = 0.f;
        for (int u = 0; u <= i; u++)
            acc = fmaf(sI[(32 + i) * 65 + 32 + u], sM[u * 33 + j], acc);
        sI[(32 + i) * 65 + j] = -acc;
    }
    __syncthreads();
    float* IL = d_invL[mb];
    for (int l = tid; l < NB * 65; l += 256) IL[l] = sI[l];
}

// ---- k_panel: P = A_block * invL^T (64x64x64 GEMM), overwrite A panel -----
__global__ __launch_bounds__(256) void k_panel(int s) {
    int mb = blockIdx.y;
    if (mb > d_kval) return;
    int sc = s * NB;
    int r0 = sc + NB + blockIdx.x * NB;
    float* A = d_A[mb];

    __shared__ float sA[NB * 65];
    __shared__ float sI[NB * 65];
    int tid = threadIdx.x;

    for (int l = tid; l < NB * NB; l += 256) {
        int r = l >> 6, c = l & 63;
        sA[r * 65 + c] = A[(size_t)(r0 + r) * P + sc + c];
    }
    const float* IL = d_invL[mb];
    for (int l = tid; l < NB * 65; l += 256) sI[l] = IL[l];
    __syncthreads();

    int tx = tid & 15, ty = tid >> 4;
    float acc[4][4];
#pragma unroll
    for (int i = 0; i < 4; i++)
#pragma unroll
        for (int j = 0; j < 4; j++) acc[i][j] = 0.f;

    // X[r][t] = sum_u A[r][u] * invL[t][u]
#pragma unroll 4
    for (int u = 0; u < NB; u++) {
        float a[4], bv[4];
#pragma unroll
        for (int q = 0; q < 4; q++) a[q] = sA[(ty * 4 + q) * 65 + u];
#pragma unroll
        for (int q = 0; q < 4; q++) bv[q] = sI[(tx * 4 + q) * 65 + u];
#pragma unroll
        for (int i = 0; i < 4; i++)
#pragma unroll
            for (int j = 0; j < 4; j++)
                acc[i][j] = fmaf(a[i], bv[j], acc[i][j]);
    }

#pragma unroll
    for (int q = 0; q < 4; q++) {
        float4 v;
        v.x = acc[q][0]; v.y = acc[q][1]; v.z = acc[q][2]; v.w = acc[q][3];
        *(float4*)&A[(size_t)(r0 + ty * 4 + q) * P + sc + tx * 4] = v;
    }
}

// ---- k_trail: C_tile -= P_i * P_j^T, one CTA per 64x64 lower tile ---------
__global__ __launch_bounds__(256) void k_trail(int s) {
    int mb = blockIdx.y;
    if (mb > d_kval) return;
    int sc = s * NB;
    int l = blockIdx.x;
    int ti = 0;
    while ((ti + 1) * (ti + 2) / 2 <= l) ti++;
    int tj = l - ti * (ti + 1) / 2;
    int ri = sc + NB + ti * NB, rj = sc + NB + tj * NB;
    float* A = d_A[mb];

    __shared__ float sPi[NB * 65];
    __shared__ float sPj[NB * 65];
    int tid = threadIdx.x;

    for (int l2 = tid; l2 < NB * NB; l2 += 256) {
        int r = l2 >> 6, c = l2 & 63;
        sPi[r * 65 + c] = A[(size_t)(ri + r) * P + sc + c];
    }
    float* Pj = sPi;
    if (ti != tj) {
        for (int l2 = tid; l2 < NB * NB; l2 += 256) {
            int r = l2 >> 6, c = l2 & 63;
            sPj[r * 65 + c] = A[(size_t)(rj + r) * P + sc + c];
        }
        Pj = sPj;
    }
    __syncthreads();

    int tx = tid & 15, ty = tid >> 4;
    float acc[4][4];
#pragma unroll
    for (int i = 0; i < 4; i++)
#pragma unroll
        for (int j = 0; j < 4; j++) acc[i][j] = 0.f;

#pragma unroll 4
    for (int u = 0; u < NB; u++) {
        float a[4], bv[4];
#pragma unroll
        for (int q = 0; q < 4; q++) a[q] = sPi[(ty * 4 + q) * 65 + u];
#pragma unroll
        for (int q = 0; q < 4; q++) bv[q] = Pj[(tx * 4 + q) * 65 + u];
#pragma unroll
        for (int i = 0; i < 4; i++)
#pragma unroll
            for (int j = 0; j < 4; j++)
                acc[i][j] = fmaf(a[i], bv[j], acc[i][j]);
    }

#pragma unroll
    for (int q = 0; q < 4; q++) {
        float* row = &A[(size_t)(ri + ty * 4 + q) * P + rj + tx * 4];
        float4 v = *(float4*)row;
        v.x -= acc[q][0]; v.y -= acc[q][1];
        v.z -= acc[q][2]; v.w -= acc[q][3];
        *(float4*)row = v;
    }
}

// ---------------- finalize: two scalars ------------------------------------
__global__ void k_final(float* out, int m) {
    if (threadIdx.x != 0) return;
    int kv = d_kval;
    double comp = 0.0;
    for (int j = 0; j < kv; j++) {
        double trPi = (double)d_cnt[j] + 1e-8;
        comp += d_hldd[j] * trPi / (double)m;
    }
    out[0] = (float)d_hldd[kv];
    out[1] = (float)comp;
}

// ---------------- launch ----------------------------------------------------
extern "C" void kernel_launch(void* const* d_in, const int* in_sizes, int n_in,
                              void* d_out, int out_size) {
    const float* X    = (const float*)d_in[0];
    const void*  Y    = d_in[1];
    const int*   ncls = (n_in >= 3) ? (const int*)d_in[2] : nullptr;
    int m = in_sizes[1];
    int p = in_sizes[0] / m;          // 512
    float* out = (float*)d_out;
    (void)out_size;

    k_init<<<1, 256>>>(ncls, (const int*)Y);
    k_prep<<<(m + 255) / 256, 256>>>(Y, m);
    k_gram<<<dim3(10, K_MAX, NSLICE), 256>>>(X, m, p);
    k_assemble<<<(P * P / 4 + 255) / 256, 256>>>(m, (float)p);
    for (int s = 0; s < NSTEP; s++) {
        k_diag<<<NM, 256>>>(s);
        int nblk = NSTEP - 1 - s;
        if (nblk > 0) {
            k_panel<<<dim3(nblk, NM), 256>>>(s);
            k_trail<<<dim3(nblk * (nblk + 1) / 2, NM), 256>>>(s);
        }
    }
    k_final<<<1, 32>>>(out, m);
}

// round 5
// speedup vs baseline: 2.1640x; 1.1226x over previous
#include <cuda_runtime.h>
#include <math.h>

#define P       512
#define K_MAX   16
#define NM      (K_MAX + 1)
#define KC      32
#define M_CAP   65536
#define NB      64
#define NSTEP   (P / NB)      // 8
#define NSLICE  3
#define DP      68            // Dinv row pitch (floats, 16B-aligned rows)

// ftrail dynamic smem: 4 buffers of 64 x 68 floats
#define FT_SMEM_BYTES (4 * NB * DP * 4)

// ---------------- device scratch (static: no allocations allowed) ----------
__device__ int    d_cnt[K_MAX];
__device__ int    d_kval;
__device__ int    d_is64;
__device__ int    d_cls[M_CAP];
__device__ float  d_Gk[NSLICE][K_MAX][P * P];
__device__ float  d_A[NM][P * P];
__device__ float  d_Dinv[NM][NB * DP];
__device__ double d_hldd[NM];

// ------- init: zero counts/hld, read num_classes, detect Y dtype -----------
__global__ void k_init(const int* ncls, const int* yw) {
    __shared__ int nz;
    int t = threadIdx.x;
    if (t == 0) nz = 0;
    __syncthreads();
    int found = 0;
    for (int i = t; i < 512; i += blockDim.x)
        if (yw[2 * i + 1] != 0) found = 1;
    if (__any_sync(0xffffffffu, found)) {
        if ((t & 31) == 0) atomicOr(&nz, 1);
    }
    __syncthreads();
    if (t < K_MAX) d_cnt[t] = 0;
    if (t < NM) d_hldd[t] = 0.0;
    if (t == 0) {
        d_is64 = nz ? 0 : 1;
        int k = ncls ? *ncls : 10;
        if (k < 1) k = 1;
        if (k > K_MAX) k = K_MAX;
        d_kval = k;
    }
}

// ---------------- prep: labels -> int32 array, class histogram --------------
__global__ void k_prep(const void* __restrict__ Y, int m) {
    int i = blockIdx.x * blockDim.x + threadIdx.x;
    if (i >= m || i >= M_CAP) return;
    int cv = d_is64 ? (int)((const long long*)Y)[i] : ((const int*)Y)[i];
    d_cls[i] = cv;
    if (cv >= 0 && cv < K_MAX) atomicAdd(&d_cnt[cv], 1);
}

// ---------------- per-class Gram (m-sliced): Gk[z][c] partial sums ---------
__global__ __launch_bounds__(256) void k_gram(const float* __restrict__ X,
                                              int m, int p) {
    int c = blockIdx.y;
    if (c >= d_kval) return;
    int tile = blockIdx.x;
    int ti = 0;
    while ((ti + 1) * (ti + 2) / 2 <= tile) ti++;
    int tj = tile - ti * (ti + 1) / 2;
    int a0 = ti * 128, b0 = tj * 128;
    int z = blockIdx.z;
    int sb = (int)((long long)m * z / NSLICE) / KC * KC;
    int se = (z == NSLICE - 1) ? m
             : (int)((long long)m * (z + 1) / NSLICE) / KC * KC;

    __shared__ __align__(16) float sA[KC][132];
    __shared__ __align__(16) float sB[KC][132];
    __shared__ int scls[KC];

    int tid = threadIdx.x;
    int tx = tid & 15, ty = tid >> 4;
    int lt = tid >> 3, lc = tid & 7;

    float acc[8][8];
#pragma unroll
    for (int i = 0; i < 8; i++)
#pragma unroll
        for (int j = 0; j < 8; j++) acc[i][j] = 0.f;

    for (int base = sb; base < se; base += KC) {
        if (tid < KC) {
            int s = base + tid;
            scls[tid] = (s < m) ? d_cls[s] : -1;
        }
        __syncthreads();
        {
            int s = base + lt;
            if (scls[lt] == c) {
                const float* xr = X + (size_t)s * p;
#pragma unroll
                for (int q = 0; q < 4; q++) {
                    int col = lc * 16 + q * 4;
                    *(float4*)&sA[lt][col] = *(const float4*)&xr[a0 + col];
                    *(float4*)&sB[lt][col] = *(const float4*)&xr[b0 + col];
                }
            }
        }
        __syncthreads();

#pragma unroll 8
        for (int t = 0; t < KC; t++) {
            if (scls[t] != c) continue;
            float a[8], b[8];
            *(float4*)&a[0] = *(const float4*)&sA[t][ty * 8];
            *(float4*)&a[4] = *(const float4*)&sA[t][ty * 8 + 4];
            *(float4*)&b[0] = *(const float4*)&sB[t][tx * 8];
            *(float4*)&b[4] = *(const float4*)&sB[t][tx * 8 + 4];
#pragma unroll
            for (int ii = 0; ii < 8; ii++)
#pragma unroll
                for (int jj = 0; jj < 8; jj++)
                    acc[ii][jj] = fmaf(a[ii], b[jj], acc[ii][jj]);
        }
        __syncthreads();
    }

    float* G = d_Gk[z][c];
    int gi = a0 + ty * 8, gj = b0 + tx * 8;
#pragma unroll
    for (int ii = 0; ii < 8; ii++) {
        *(float4*)&G[(size_t)(gi + ii) * P + gj]     = *(float4*)&acc[ii][0];
        *(float4*)&G[(size_t)(gi + ii) * P + gj + 4] = *(float4*)&acc[ii][4];
    }
    if (ti != tj) {
#pragma unroll
        for (int ii = 0; ii < 8; ii++)
#pragma unroll
            for (int jj = 0; jj < 8; jj++)
                G[(size_t)(gj + jj) * P + gi + ii] = acc[ii][jj];
    }
}

// --------- assemble A_j = I + scal_j*(sum slices), A_kv = I + scalar*G -----
__global__ __launch_bounds__(256) void k_assemble(int m, float pf) {
    int idx4 = blockIdx.x * blockDim.x + threadIdx.x;
    if (idx4 >= P * P / 4) return;
    int idx = idx4 * 4;
    int r = idx >> 9, c0 = idx & 511;
    int kv = d_kval;
    float dg[4];
#pragma unroll
    for (int q = 0; q < 4; q++) dg[q] = (r == c0 + q) ? 1.f : 0.f;
    float sum[4] = {0.f, 0.f, 0.f, 0.f};
    for (int j = 0; j < kv; j++) {
        float4 g0 = *(const float4*)&d_Gk[0][j][idx];
        float4 g1 = *(const float4*)&d_Gk[1][j][idx];
        float4 g2 = *(const float4*)&d_Gk[2][j][idx];
        float g[4];
        g[0] = g0.x + g1.x + g2.x; g[1] = g0.y + g1.y + g2.y;
        g[2] = g0.z + g1.z + g2.z; g[3] = g0.w + g1.w + g2.w;
        float scal = pf / (((float)d_cnt[j] + 1e-8f) * 0.01f);
        float4 o;
        o.x = dg[0] + scal * g[0]; o.y = dg[1] + scal * g[1];
        o.z = dg[2] + scal * g[2]; o.w = dg[3] + scal * g[3];
        *(float4*)&d_A[j][idx] = o;
#pragma unroll
        for (int q = 0; q < 4; q++) sum[q] += g[q];
    }
    float scalar = pf / ((float)m * 0.01f);
    float4 o;
    o.x = dg[0] + scalar * sum[0]; o.y = dg[1] + scalar * sum[1];
    o.z = dg[2] + scalar * sum[2]; o.w = dg[3] + scalar * sum[3];
    *(float4*)&d_A[kv][idx] = o;
}

// ---- k_diag: rank-8 blocked 64x64 factor, logdet, invL, Dinv --------------
__global__ __launch_bounds__(256) void k_diag(int s) {
    int mb = blockIdx.x;
    if (mb > d_kval) return;
    float* A = d_A[mb];
    int sc = s * NB;

    __shared__ float sD[NB * 65];
    __shared__ float sI[NB * 65];
    __shared__ float sM[32 * 33];
    __shared__ float sdinv[NB];
    __shared__ float sRed[NB];
    int tid = threadIdx.x;

    for (int l = tid; l < NB * NB; l += 256) {
        int r = l >> 6, c = l & 63;
        sD[r * 65 + c] = A[(size_t)(sc + r) * P + sc + c];
    }
    for (int l = tid; l < NB * 65; l += 256) sI[l] = 0.f;
    __syncthreads();

    // ---- rank-8 blocked right-looking factor of lower 64x64 ----
#pragma unroll 1
    for (int b = 0; b < NB; b += 8) {
        // warp 0: factor the 8x8 diag sub-block
        if (tid < 32) {
#pragma unroll
            for (int t = 0; t < 8; t++) {
                int tt = b + t;
                if (tid == 0) sD[tt * 65 + tt] = sqrtf(sD[tt * 65 + tt]);
                __syncwarp();
                float dinv = 1.f / sD[tt * 65 + tt];
                if (tid > t && tid < 8)
                    sD[(b + tid) * 65 + tt] *= dinv;
                __syncwarp();
                int i = tid >> 2, u = tid & 3;     // 8x4 coverage, 2 passes
#pragma unroll
                for (int pass = 0; pass < 2; pass++) {
                    int uu = u + pass * 4;
                    if (uu > t && i >= uu)
                        sD[(b + i) * 65 + b + uu] =
                            fmaf(-sD[(b + i) * 65 + tt],
                                 sD[(b + uu) * 65 + tt],
                                 sD[(b + i) * 65 + b + uu]);
                }
                __syncwarp();
            }
        }
        __syncthreads();

        int rows = NB - b - 8;
        if (rows > 0) {
            // panel solve: thread r solves its row against the 8x8 L block
            if (tid < rows) {
                int r = b + 8 + tid;
                float x[8];
#pragma unroll
                for (int t = 0; t < 8; t++) x[t] = sD[r * 65 + b + t];
#pragma unroll
                for (int t = 0; t < 8; t++) {
                    float v = x[t];
#pragma unroll
                    for (int u = 0; u < t; u++)
                        v = fmaf(-x[u], sD[(b + t) * 65 + b + u], v);
                    x[t] = v / sD[(b + t) * 65 + b + t];
                }
#pragma unroll
                for (int t = 0; t < 8; t++) sD[r * 65 + b + t] = x[t];
            }
            __syncthreads();

            // rank-8 symmetric update of trailing square (write full square)
            for (int l = tid; l < rows * rows; l += 256) {
                int i = b + 8 + l / rows, u = b + 8 + l % rows;
                float acc = sD[i * 65 + u];
#pragma unroll
                for (int t = 0; t < 8; t++)
                    acc = fmaf(-sD[i * 65 + b + t], sD[u * 65 + b + t], acc);
                sD[i * 65 + u] = acc;
            }
        }
        __syncthreads();
    }

    if (tid < NB) {
        sRed[tid] = logf(sD[tid * 65 + tid]);
        sdinv[tid] = 1.f / sD[tid * 65 + tid];
    }
    __syncthreads();
    if (tid == 0) {
        double acc = 0.0;
        for (int t = 0; t < NB; t++) acc += (double)sRed[t];
        d_hldd[mb] += acc;
    }

    // blocked triangular inverse: inv11/inv22 (32x32) then off-diag block
    if (tid < 64) {
        int half = tid >> 5, c = tid & 31, b = half * 32;
        for (int i = c; i < 32; i++) {
            float acc = (i == c) ? 1.f : 0.f;
            for (int u = c; u < i; u++)
                acc = fmaf(-sD[(b + i) * 65 + b + u], sI[(b + u) * 65 + b + c],
                           acc);
            sI[(b + i) * 65 + b + c] = acc * sdinv[b + i];
        }
    }
    __syncthreads();
    for (int l = tid; l < 32 * 32; l += 256) {
        int i = l >> 5, j = l & 31;
        float acc = 0.f;
        for (int u = j; u < 32; u++)
            acc = fmaf(sD[(32 + i) * 65 + u], sI[u * 65 + j], acc);
        sM[i * 33 + j] = acc;
    }
    __syncthreads();
    for (int l = tid; l < 32 * 32; l += 256) {
        int i = l >> 5, j = l & 31;
        float acc = 0.f;
        for (int u = 0; u <= i; u++)
            acc = fmaf(sI[(32 + i) * 65 + 32 + u], sM[u * 33 + j], acc);
        sI[(32 + i) * 65 + j] = -acc;
    }
    __syncthreads();

    // Dinv = invL^T * invL  (symmetric), store global with pitch DP
    float* DI = d_Dinv[mb];
    for (int l = tid; l < NB * NB; l += 256) {
        int t = l >> 6, u = l & 63;
        int w0 = t > u ? t : u;
        float acc = 0.f;
        for (int w = w0; w < NB; w++)
            acc = fmaf(sI[w * 65 + t], sI[w * 65 + u], acc);
        DI[t * DP + u] = acc;
    }
}

// ---- k_ftrail: C_ij -= A_i * Dinv * A_j^T, one CTA per 64x64 lower tile ---
__global__ __launch_bounds__(256) void k_ftrail(int s) {
    int mb = blockIdx.y;
    if (mb > d_kval) return;
    int sc = s * NB;
    int l = blockIdx.x;
    int ti = 0;
    while ((ti + 1) * (ti + 2) / 2 <= l) ti++;
    int tj = l - ti * (ti + 1) / 2;
    int ri = sc + NB + ti * NB, rj = sc + NB + tj * NB;
    float* A = d_A[mb];

    extern __shared__ float fs[];
    float* sDv  = fs;                 // [64][DP] Dinv (symmetric)
    float* sAjT = fs + NB * DP;       // [u][j]
    float* sAiT = fs + 2 * NB * DP;   // [t][i]
    float* sT   = fs + 3 * NB * DP;   // [t][j]

    int tid = threadIdx.x;

    // load Dinv rows (coalesced)
    {
        const float* DI = d_Dinv[mb];
        for (int q = tid; q < NB * DP / 4; q += 256)
            *(float4*)&sDv[q * 4] = *(const float4*)&DI[q * 4];
    }
    // load + transpose A_j and A_i blocks
    {
        int j = tid >> 2, u0 = (tid & 3) * 16;
        const float* rowj = &A[(size_t)(rj + j) * P + sc];
        const float* rowi = &A[(size_t)(ri + j) * P + sc];
#pragma unroll
        for (int q4 = 0; q4 < 4; q4++) {
            float4 vj = *(const float4*)&rowj[u0 + q4 * 4];
            float4 vi = *(const float4*)&rowi[u0 + q4 * 4];
            int u = u0 + q4 * 4;
            sAjT[(u + 0) * DP + j] = vj.x; sAjT[(u + 1) * DP + j] = vj.y;
            sAjT[(u + 2) * DP + j] = vj.z; sAjT[(u + 3) * DP + j] = vj.w;
            sAiT[(u + 0) * DP + j] = vi.x; sAiT[(u + 1) * DP + j] = vi.y;
            sAiT[(u + 2) * DP + j] = vi.z; sAiT[(u + 3) * DP + j] = vi.w;
        }
    }
    __syncthreads();

    int tx = tid & 15, ty = tid >> 4;

    // GEMM1: T[t][j] = sum_u Dinv[t][u] * A_j[j][u]
    {
        float acc[4][4];
#pragma unroll
        for (int i = 0; i < 4; i++)
#pragma unroll
            for (int j = 0; j < 4; j++) acc[i][j] = 0.f;
#pragma unroll 8
        for (int u = 0; u < NB; u++) {
            float4 a = *(const float4*)&sDv[u * DP + ty * 4];
            float4 b = *(const float4*)&sAjT[u * DP + tx * 4];
            float av[4] = {a.x, a.y, a.z, a.w};
            float bv[4] = {b.x, b.y, b.z, b.w};
#pragma unroll
            for (int i = 0; i < 4; i++)
#pragma unroll
                for (int j = 0; j < 4; j++)
                    acc[i][j] = fmaf(av[i], bv[j], acc[i][j]);
        }
#pragma unroll
        for (int i = 0; i < 4; i++) {
            float4 v;
            v.x = acc[i][0]; v.y = acc[i][1]; v.z = acc[i][2]; v.w = acc[i][3];
            *(float4*)&sT[(ty * 4 + i) * DP + tx * 4] = v;
        }
    }
    __syncthreads();

    // GEMM2: C[i][j] -= sum_t A_i[i][t] * T[t][j]
    {
        float acc[4][4];
#pragma unroll
        for (int i = 0; i < 4; i++)
#pragma unroll
            for (int j = 0; j < 4; j++) acc[i][j] = 0.f;
#pragma unroll 8
        for (int t = 0; t < NB; t++) {
            float4 a = *(const float4*)&sAiT[t * DP + ty * 4];
            float4 b = *(const float4*)&sT[t * DP + tx * 4];
            float av[4] = {a.x, a.y, a.z, a.w};
            float bv[4] = {b.x, b.y, b.z, b.w};
#pragma unroll
            for (int i = 0; i < 4; i++)
#pragma unroll
                for (int j = 0; j < 4; j++)
                    acc[i][j] = fmaf(av[i], bv[j], acc[i][j]);
        }
#pragma unroll
        for (int q = 0; q < 4; q++) {
            float* row = &A[(size_t)(ri + ty * 4 + q) * P + rj + tx * 4];
            float4 v = *(float4*)row;
            v.x -= acc[q][0]; v.y -= acc[q][1];
            v.z -= acc[q][2]; v.w -= acc[q][3];
            *(float4*)row = v;
        }
    }
}

// ---------------- finalize: two scalars ------------------------------------
__global__ void k_final(float* out, int m) {
    if (threadIdx.x != 0) return;
    int kv = d_kval;
    double comp = 0.0;
    for (int j = 0; j < kv; j++) {
        double trPi = (double)d_cnt[j] + 1e-8;
        comp += d_hldd[j] * trPi / (double)m;
    }
    out[0] = (float)d_hldd[kv];
    out[1] = (float)comp;
}

// ---------------- launch ----------------------------------------------------
extern "C" void kernel_launch(void* const* d_in, const int* in_sizes, int n_in,
                              void* d_out, int out_size) {
    const float* X    = (const float*)d_in[0];
    const void*  Y    = d_in[1];
    const int*   ncls = (n_in >= 3) ? (const int*)d_in[2] : nullptr;
    int m = in_sizes[1];
    int p = in_sizes[0] / m;          // 512
    float* out = (float*)d_out;
    (void)out_size;

    cudaFuncSetAttribute(k_ftrail, cudaFuncAttributeMaxDynamicSharedMemorySize,
                         FT_SMEM_BYTES);

    k_init<<<1, 256>>>(ncls, (const int*)Y);
    k_prep<<<(m + 255) / 256, 256>>>(Y, m);
    k_gram<<<dim3(10, K_MAX, NSLICE), 256>>>(X, m, p);
    k_assemble<<<(P * P / 4 + 255) / 256, 256>>>(m, (float)p);
    for (int s = 0; s < NSTEP; s++) {
        k_diag<<<NM, 256>>>(s);
        int nblk = NSTEP - 1 - s;
        if (nblk > 0)
            k_ftrail<<<dim3(nblk * (nblk + 1) / 2, NM), 256,
                       FT_SMEM_BYTES>>>(s);
    }
    k_final<<<1, 32>>>(out, m);
}

// round 6
// speedup vs baseline: 2.3069x; 1.0660x over previous
#include <cuda_runtime.h>
#include <math.h>

#define P       512
#define K_MAX   16
#define NM      (K_MAX + 1)
#define KC      32
#define M_CAP   65536
#define NB      64
#define NSTEP   (P / NB)      // 8
#define NSLICE  3
#define DP      68            // Dinv row pitch (floats, 16B-aligned rows)

// ftrail dynamic smem: 4 buffers of 64 x 68 floats
#define FT_SMEM_BYTES (4 * NB * DP * 4)

typedef unsigned long long ull;

// ---------------- f32x2 packed helpers (Blackwell sm_103a) -----------------
__device__ __forceinline__ ull ffma2(ull a, ull b, ull c) {
    ull d;
    asm("fma.rn.f32x2 %0, %1, %2, %3;" : "=l"(d) : "l"(a), "l"(b), "l"(c));
    return d;
}
__device__ __forceinline__ ull dup2(float x) {
    ull r; unsigned xb = __float_as_uint(x);
    asm("mov.b64 %0, {%1, %2};" : "=l"(r) : "r"(xb), "r"(xb));
    return r;
}
__device__ __forceinline__ ull pack2(float lo, float hi) {
    ull r;
    asm("mov.b64 %0, {%1, %2};" : "=l"(r) : "f"(lo), "f"(hi));
    return r;
}
__device__ __forceinline__ float2 unpk2(ull v) {
    float2 r;
    asm("mov.b64 {%0, %1}, %2;" : "=f"(r.x), "=f"(r.y) : "l"(v));
    return r;
}

// ---------------- device scratch (static: no allocations allowed) ----------
__device__ int    d_cnt[K_MAX];
__device__ int    d_kval;
__device__ int    d_is64;
__device__ int    d_cls[M_CAP];
__device__ float  d_Gk[NSLICE][K_MAX][P * P];
__device__ float  d_A[NM][P * P];
__device__ float  d_Dinv[NM][NB * DP];
__device__ double d_hldd[NM];

// ------- init: zero counts/hld, read num_classes, detect Y dtype -----------
__global__ void k_init(const int* ncls, const int* yw) {
    __shared__ int nz;
    int t = threadIdx.x;
    if (t == 0) nz = 0;
    __syncthreads();
    int found = 0;
    for (int i = t; i < 512; i += blockDim.x)
        if (yw[2 * i + 1] != 0) found = 1;
    if (__any_sync(0xffffffffu, found)) {
        if ((t & 31) == 0) atomicOr(&nz, 1);
    }
    __syncthreads();
    if (t < K_MAX) d_cnt[t] = 0;
    if (t < NM) d_hldd[t] = 0.0;
    if (t == 0) {
        d_is64 = nz ? 0 : 1;
        int k = ncls ? *ncls : 10;
        if (k < 1) k = 1;
        if (k > K_MAX) k = K_MAX;
        d_kval = k;
    }
}

// ---------------- prep: labels -> int32 array, class histogram --------------
__global__ void k_prep(const void* __restrict__ Y, int m) {
    int i = blockIdx.x * blockDim.x + threadIdx.x;
    if (i >= m || i >= M_CAP) return;
    int cv = d_is64 ? (int)((const long long*)Y)[i] : ((const int*)Y)[i];
    d_cls[i] = cv;
    if (cv >= 0 && cv < K_MAX) atomicAdd(&d_cnt[cv], 1);
}

// ---------------- per-class Gram (m-sliced, f32x2 inner) -------------------
__global__ __launch_bounds__(256) void k_gram(const float* __restrict__ X,
                                              int m, int p) {
    int c = blockIdx.y;
    if (c >= d_kval) return;
    int tile = blockIdx.x;
    int ti = 0;
    while ((ti + 1) * (ti + 2) / 2 <= tile) ti++;
    int tj = tile - ti * (ti + 1) / 2;
    int a0 = ti * 128, b0 = tj * 128;
    int z = blockIdx.z;
    int sb = (int)((long long)m * z / NSLICE) / KC * KC;
    int se = (z == NSLICE - 1) ? m
             : (int)((long long)m * (z + 1) / NSLICE) / KC * KC;

    __shared__ __align__(16) float sA[KC][132];
    __shared__ __align__(16) float sB[KC][132];
    __shared__ int scls[KC];

    int tid = threadIdx.x;
    int tx = tid & 15, ty = tid >> 4;
    int lt = tid >> 3, lc = tid & 7;

    ull acc2[8][4];
#pragma unroll
    for (int i = 0; i < 8; i++)
#pragma unroll
        for (int q = 0; q < 4; q++) acc2[i][q] = 0ull;

    for (int base = sb; base < se; base += KC) {
        if (tid < KC) {
            int s = base + tid;
            scls[tid] = (s < m) ? d_cls[s] : -1;
        }
        __syncthreads();
        {
            int s = base + lt;
            if (scls[lt] == c) {
                const float* xr = X + (size_t)s * p;
#pragma unroll
                for (int q = 0; q < 4; q++) {
                    int col = lc * 16 + q * 4;
                    *(float4*)&sA[lt][col] = *(const float4*)&xr[a0 + col];
                    *(float4*)&sB[lt][col] = *(const float4*)&xr[b0 + col];
                }
            }
        }
        __syncthreads();

#pragma unroll 4
        for (int t = 0; t < KC; t++) {
            if (scls[t] != c) continue;
            float a[8];
            ull ad[8], b2[4];
            *(float4*)&a[0] = *(const float4*)&sA[t][ty * 8];
            *(float4*)&a[4] = *(const float4*)&sA[t][ty * 8 + 4];
#pragma unroll
            for (int i = 0; i < 8; i++) ad[i] = dup2(a[i]);
#pragma unroll
            for (int q = 0; q < 4; q++)
                b2[q] = *(const ull*)&sB[t][tx * 2 + q * 32];
#pragma unroll
            for (int i = 0; i < 8; i++)
#pragma unroll
                for (int q = 0; q < 4; q++)
                    acc2[i][q] = ffma2(ad[i], b2[q], acc2[i][q]);
        }
        __syncthreads();
    }

    float* G = d_Gk[z][c];
    int gi = a0 + ty * 8;
#pragma unroll
    for (int i = 0; i < 8; i++)
#pragma unroll
        for (int q = 0; q < 4; q++) {
            float2 v = unpk2(acc2[i][q]);
            int col = b0 + q * 32 + tx * 2;
            *(float2*)&G[(size_t)(gi + i) * P + col] = v;
        }
    if (ti != tj) {
#pragma unroll
        for (int i = 0; i < 8; i++)
#pragma unroll
            for (int q = 0; q < 4; q++) {
                float2 v = unpk2(acc2[i][q]);
                int col = b0 + q * 32 + tx * 2;
                G[(size_t)col * P + gi + i]       = v.x;
                G[(size_t)(col + 1) * P + gi + i] = v.y;
            }
    }
}

// --------- assemble A_j = I + scal_j*(sum slices), A_kv = I + scalar*G -----
__global__ __launch_bounds__(256) void k_assemble(int m, float pf) {
    int idx4 = blockIdx.x * blockDim.x + threadIdx.x;
    if (idx4 >= P * P / 4) return;
    int idx = idx4 * 4;
    int r = idx >> 9, c0 = idx & 511;
    int kv = d_kval;
    float dg[4];
#pragma unroll
    for (int q = 0; q < 4; q++) dg[q] = (r == c0 + q) ? 1.f : 0.f;
    float sum[4] = {0.f, 0.f, 0.f, 0.f};
    for (int j = 0; j < kv; j++) {
        float4 g0 = *(const float4*)&d_Gk[0][j][idx];
        float4 g1 = *(const float4*)&d_Gk[1][j][idx];
        float4 g2 = *(const float4*)&d_Gk[2][j][idx];
        float g[4];
        g[0] = g0.x + g1.x + g2.x; g[1] = g0.y + g1.y + g2.y;
        g[2] = g0.z + g1.z + g2.z; g[3] = g0.w + g1.w + g2.w;
        float scal = pf / (((float)d_cnt[j] + 1e-8f) * 0.01f);
        float4 o;
        o.x = dg[0] + scal * g[0]; o.y = dg[1] + scal * g[1];
        o.z = dg[2] + scal * g[2]; o.w = dg[3] + scal * g[3];
        *(float4*)&d_A[j][idx] = o;
#pragma unroll
        for (int q = 0; q < 4; q++) sum[q] += g[q];
    }
    float scalar = pf / ((float)m * 0.01f);
    float4 o;
    o.x = dg[0] + scalar * sum[0]; o.y = dg[1] + scalar * sum[1];
    o.z = dg[2] + scalar * sum[2]; o.w = dg[3] + scalar * sum[3];
    *(float4*)&d_A[kv][idx] = o;
}

// ---- k_diag: rank-8 factor, logdet, Z=L^-1 (rank-8 panels), Dinv=Z^T Z ----
__global__ __launch_bounds__(256) void k_diag(int s) {
    int mb = blockIdx.x;
    if (mb > d_kval) return;
    float* A = d_A[mb];
    int sc = s * NB;

    __shared__ float sD[NB * 65];
    __shared__ float sZ[NB * 65];
    __shared__ float sW[8 * 64];
    __shared__ float sdinv[NB];
    __shared__ float sRed[NB];
    int tid = threadIdx.x;
    bool needZ = (s < NSTEP - 1);

    for (int l = tid; l < NB * NB; l += 256) {
        int r = l >> 6, c = l & 63;
        sD[r * 65 + c] = A[(size_t)(sc + r) * P + sc + c];
    }
    if (needZ)
        for (int l = tid; l < NB * 65; l += 256) sZ[l] = 0.f;
    __syncthreads();

    // ---- rank-8 blocked right-looking factor of lower 64x64 ----
#pragma unroll 1
    for (int b = 0; b < NB; b += 8) {
        if (tid < 32) {
#pragma unroll
            for (int t = 0; t < 8; t++) {
                int tt = b + t;
                if (tid == 0) sD[tt * 65 + tt] = sqrtf(sD[tt * 65 + tt]);
                __syncwarp();
                float dinv = 1.f / sD[tt * 65 + tt];
                if (tid > t && tid < 8)
                    sD[(b + tid) * 65 + tt] *= dinv;
                __syncwarp();
                int i = tid >> 2, u = tid & 3;
#pragma unroll
                for (int pass = 0; pass < 2; pass++) {
                    int uu = u + pass * 4;
                    if (uu > t && i >= uu)
                        sD[(b + i) * 65 + b + uu] =
                            fmaf(-sD[(b + i) * 65 + tt],
                                 sD[(b + uu) * 65 + tt],
                                 sD[(b + i) * 65 + b + uu]);
                }
                __syncwarp();
            }
        }
        __syncthreads();

        int rows = NB - b - 8;
        if (rows > 0) {
            if (tid < rows) {
                int r = b + 8 + tid;
                float x[8];
#pragma unroll
                for (int t = 0; t < 8; t++) x[t] = sD[r * 65 + b + t];
#pragma unroll
                for (int t = 0; t < 8; t++) {
                    float v = x[t];
#pragma unroll
                    for (int u = 0; u < t; u++)
                        v = fmaf(-x[u], sD[(b + t) * 65 + b + u], v);
                    x[t] = v / sD[(b + t) * 65 + b + t];
                }
#pragma unroll
                for (int t = 0; t < 8; t++) sD[r * 65 + b + t] = x[t];
            }
            __syncthreads();

            for (int l = tid; l < rows * rows; l += 256) {
                int i = b + 8 + l / rows, u = b + 8 + l % rows;
                float acc = sD[i * 65 + u];
#pragma unroll
                for (int t = 0; t < 8; t++)
                    acc = fmaf(-sD[i * 65 + b + t], sD[u * 65 + b + t], acc);
                sD[i * 65 + u] = acc;
            }
        }
        __syncthreads();
    }

    if (tid < NB) {
        float dv = sD[tid * 65 + tid];
        sRed[tid] = logf(dv);
        sdinv[tid] = 1.f / dv;
    }
    __syncthreads();
    if (tid == 0) {
        double acc = 0.0;
        for (int t = 0; t < NB; t++) acc += (double)sRed[t];
        d_hldd[mb] += acc;
    }
    if (!needZ) return;

    // ---- Z = L^{-1}: rank-8 panels, columns parallel, GEMM part 256-wide ---
    for (int b = 0; b < NB; b += 8) {
        {
            int t0 = tid >> 6;          // 0..3
            int j = tid & 63;
#pragma unroll
            for (int pass = 0; pass < 2; pass++) {
                int t = t0 + pass * 4;
                float acc = 0.f;
                for (int u = 0; u < b; u++)
                    acc = fmaf(sD[(b + t) * 65 + u], sZ[u * 65 + j], acc);
                sW[t * 64 + j] = acc;
            }
        }
        __syncthreads();
        if (tid < 64) {
            int j = tid;
#pragma unroll
            for (int t = 0; t < 8; t++) {
                int r = b + t;
                if (j <= r) {
                    float v = ((r == j) ? 1.f : 0.f) - sW[t * 64 + j];
#pragma unroll
                    for (int u = 0; u < 8; u++) {
                        if (u < t)
                            v = fmaf(-sD[r * 65 + b + u], sZ[(b + u) * 65 + j],
                                     v);
                    }
                    sZ[r * 65 + j] = v * sdinv[r];
                }
            }
        }
        __syncthreads();
    }

    // ---- Dinv = Z^T Z ----
    float* DI = d_Dinv[mb];
    for (int l = tid; l < NB * NB; l += 256) {
        int t = l >> 6, u = l & 63;
        int w0 = t > u ? t : u;
        float acc = 0.f;
        for (int w = w0; w < NB; w++)
            acc = fmaf(sZ[w * 65 + t], sZ[w * 65 + u], acc);
        DI[t * DP + u] = acc;
    }
}

// ---- k_ftrail: C_ij -= A_i * Dinv * A_j^T (f32x2 GEMMs) -------------------
__global__ __launch_bounds__(256) void k_ftrail(int s) {
    int mb = blockIdx.y;
    if (mb > d_kval) return;
    int sc = s * NB;
    int l = blockIdx.x;
    int ti = 0;
    while ((ti + 1) * (ti + 2) / 2 <= l) ti++;
    int tj = l - ti * (ti + 1) / 2;
    int ri = sc + NB + ti * NB, rj = sc + NB + tj * NB;
    float* A = d_A[mb];

    extern __shared__ float fs[];
    float* sDv  = fs;                 // [64][DP] Dinv
    float* sAjT = fs + NB * DP;       // [u][j]
    float* sAiT = fs + 2 * NB * DP;   // [t][i]
    float* sT   = fs + 3 * NB * DP;   // [t][j]

    int tid = threadIdx.x;

    {
        const float* DI = d_Dinv[mb];
        for (int q = tid; q < NB * DP / 4; q += 256)
            *(float4*)&sDv[q * 4] = *(const float4*)&DI[q * 4];
    }
    {
        int j = tid >> 2, u0 = (tid & 3) * 16;
        const float* rowj = &A[(size_t)(rj + j) * P + sc];
        const float* rowi = &A[(size_t)(ri + j) * P + sc];
#pragma unroll
        for (int q4 = 0; q4 < 4; q4++) {
            float4 vj = *(const float4*)&rowj[u0 + q4 * 4];
            float4 vi = *(const float4*)&rowi[u0 + q4 * 4];
            int u = u0 + q4 * 4;
            sAjT[(u + 0) * DP + j] = vj.x; sAjT[(u + 1) * DP + j] = vj.y;
            sAjT[(u + 2) * DP + j] = vj.z; sAjT[(u + 3) * DP + j] = vj.w;
            sAiT[(u + 0) * DP + j] = vi.x; sAiT[(u + 1) * DP + j] = vi.y;
            sAiT[(u + 2) * DP + j] = vi.z; sAiT[(u + 3) * DP + j] = vi.w;
        }
    }
    __syncthreads();

    int tx = tid & 15, ty = tid >> 4;

    // GEMM1: T[t][j] = sum_u Dinv[t][u] * A_j[j][u]
    {
        ull acc2[4][2];
#pragma unroll
        for (int i = 0; i < 4; i++) { acc2[i][0] = 0ull; acc2[i][1] = 0ull; }
#pragma unroll 8
        for (int u = 0; u < NB; u++) {
            float4 av = *(const float4*)&sDv[u * DP + ty * 4];
            float4 bv = *(const float4*)&sAjT[u * DP + tx * 4];
            ull b0 = pack2(bv.x, bv.y), b1 = pack2(bv.z, bv.w);
            ull a0 = dup2(av.x), a1 = dup2(av.y);
            ull a2 = dup2(av.z), a3 = dup2(av.w);
            acc2[0][0] = ffma2(a0, b0, acc2[0][0]);
            acc2[0][1] = ffma2(a0, b1, acc2[0][1]);
            acc2[1][0] = ffma2(a1, b0, acc2[1][0]);
            acc2[1][1] = ffma2(a1, b1, acc2[1][1]);
            acc2[2][0] = ffma2(a2, b0, acc2[2][0]);
            acc2[2][1] = ffma2(a2, b1, acc2[2][1]);
            acc2[3][0] = ffma2(a3, b0, acc2[3][0]);
            acc2[3][1] = ffma2(a3, b1, acc2[3][1]);
        }
#pragma unroll
        for (int i = 0; i < 4; i++) {
            float2 lo = unpk2(acc2[i][0]), hi = unpk2(acc2[i][1]);
            float4 v; v.x = lo.x; v.y = lo.y; v.z = hi.x; v.w = hi.y;
            *(float4*)&sT[(ty * 4 + i) * DP + tx * 4] = v;
        }
    }
    __syncthreads();

    // GEMM2: C[i][j] -= sum_t A_i[i][t] * T[t][j]
    {
        ull acc2[4][2];
#pragma unroll
        for (int i = 0; i < 4; i++) { acc2[i][0] = 0ull; acc2[i][1] = 0ull; }
#pragma unroll 8
        for (int t = 0; t < NB; t++) {
            float4 av = *(const float4*)&sAiT[t * DP + ty * 4];
            float4 bv = *(const float4*)&sT[t * DP + tx * 4];
            ull b0 = pack2(bv.x, bv.y), b1 = pack2(bv.z, bv.w);
            ull a0 = dup2(av.x), a1 = dup2(av.y);
            ull a2 = dup2(av.z), a3 = dup2(av.w);
            acc2[0][0] = ffma2(a0, b0, acc2[0][0]);
            acc2[0][1] = ffma2(a0, b1, acc2[0][1]);
            acc2[1][0] = ffma2(a1, b0, acc2[1][0]);
            acc2[1][1] = ffma2(a1, b1, acc2[1][1]);
            acc2[2][0] = ffma2(a2, b0, acc2[2][0]);
            acc2[2][1] = ffma2(a2, b1, acc2[2][1]);
            acc2[3][0] = ffma2(a3, b0, acc2[3][0]);
            acc2[3][1] = ffma2(a3, b1, acc2[3][1]);
        }
#pragma unroll
        for (int q = 0; q < 4; q++) {
            float2 lo = unpk2(acc2[q][0]), hi = unpk2(acc2[q][1]);
            float* row = &A[(size_t)(ri + ty * 4 + q) * P + rj + tx * 4];
            float4 v = *(float4*)row;
            v.x -= lo.x; v.y -= lo.y; v.z -= hi.x; v.w -= hi.y;
            *(float4*)row = v;
        }
    }
}

// ---------------- finalize: two scalars ------------------------------------
__global__ void k_final(float* out, int m) {
    if (threadIdx.x != 0) return;
    int kv = d_kval;
    double comp = 0.0;
    for (int j = 0; j < kv; j++) {
        double trPi = (double)d_cnt[j] + 1e-8;
        comp += d_hldd[j] * trPi / (double)m;
    }
    out[0] = (float)d_hldd[kv];
    out[1] = (float)comp;
}

// ---------------- launch ----------------------------------------------------
extern "C" void kernel_launch(void* const* d_in, const int* in_sizes, int n_in,
                              void* d_out, int out_size) {
    const float* X    = (const float*)d_in[0];
    const void*  Y    = d_in[1];
    const int*   ncls = (n_in >= 3) ? (const int*)d_in[2] : nullptr;
    int m = in_sizes[1];
    int p = in_sizes[0] / m;          // 512
    float* out = (float*)d_out;
    (void)out_size;

    cudaFuncSetAttribute(k_ftrail, cudaFuncAttributeMaxDynamicSharedMemorySize,
                         FT_SMEM_BYTES);

    k_init<<<1, 256>>>(ncls, (const int*)Y);
    k_prep<<<(m + 255) / 256, 256>>>(Y, m);
    k_gram<<<dim3(10, K_MAX, NSLICE), 256>>>(X, m, p);
    k_assemble<<<(P * P / 4 + 255) / 256, 256>>>(m, (float)p);
    for (int s = 0; s < NSTEP; s++) {
        k_diag<<<NM, 256>>>(s);
        int nblk = NSTEP - 1 - s;
        if (nblk > 0)
            k_ftrail<<<dim3(nblk * (nblk + 1) / 2, NM), 256,
                       FT_SMEM_BYTES>>>(s);
    }
    k_final<<<1, 32>>>(out, m);
}

// round 7
// speedup vs baseline: 2.8319x; 1.2276x over previous
#include <cuda_runtime.h>
#include <math.h>

#define P       512
#define K_MAX   16
#define NM      (K_MAX + 1)
#define M_CAP   65536
#define NCH_MAX 256           // max chunks of 256 samples
#define NB      64
#define NSTEP   (P / NB)      // 8
#define NSLICE  3
#define DP      68

#define FT_SMEM_BYTES (4 * NB * DP * 4)

typedef unsigned long long ull;

// ---------------- f32x2 packed helpers (Blackwell sm_103a) -----------------
__device__ __forceinline__ ull ffma2(ull a, ull b, ull c) {
    ull d;
    asm("fma.rn.f32x2 %0, %1, %2, %3;" : "=l"(d) : "l"(a), "l"(b), "l"(c));
    return d;
}
__device__ __forceinline__ ull dup2(float x) {
    ull r; unsigned xb = __float_as_uint(x);
    asm("mov.b64 %0, {%1, %2};" : "=l"(r) : "r"(xb), "r"(xb));
    return r;
}
__device__ __forceinline__ ull pack2(float lo, float hi) {
    ull r;
    asm("mov.b64 %0, {%1, %2};" : "=l"(r) : "f"(lo), "f"(hi));
    return r;
}
__device__ __forceinline__ float2 unpk2(ull v) {
    float2 r;
    asm("mov.b64 {%0, %1}, %2;" : "=f"(r.x), "=f"(r.y) : "l"(v));
    return r;
}

// ---------------- device scratch -------------------------------------------
__device__ int    d_cnt[K_MAX];
__device__ int    d_kval;
__device__ int    d_is64;
__device__ int    d_cls[M_CAP];
__device__ int    d_idx[M_CAP];
__device__ int    d_bh[NCH_MAX][K_MAX];     // per-chunk histogram
__device__ int    d_boff[NCH_MAX][K_MAX];   // per-chunk exclusive offset
__device__ int    d_cstart[K_MAX];
__device__ float  d_Gk[NSLICE][K_MAX][P * P];
__device__ float  d_A[NM][P * P];
__device__ float  d_Dinv[NM][NB * DP];
__device__ double d_hldd[NM];

// ------- init: read num_classes, detect Y dtype, zero hld ------------------
__global__ void k_init(const int* ncls, const int* yw) {
    __shared__ int nz;
    int t = threadIdx.x;
    if (t == 0) nz = 0;
    __syncthreads();
    int found = 0;
    for (int i = t; i < 512; i += blockDim.x)
        if (yw[2 * i + 1] != 0) found = 1;
    if (__any_sync(0xffffffffu, found)) {
        if ((t & 31) == 0) atomicOr(&nz, 1);
    }
    __syncthreads();
    if (t < NM) d_hldd[t] = 0.0;
    if (t == 0) {
        d_is64 = nz ? 0 : 1;
        int k = ncls ? *ncls : 10;
        if (k < 1) k = 1;
        if (k > K_MAX) k = K_MAX;
        d_kval = k;
    }
}

// ------- prep: labels -> int32, per-chunk histogram ------------------------
__global__ void k_prep(const void* __restrict__ Y, int m) {
    __shared__ int sh[K_MAX];
    int tid = threadIdx.x;
    if (tid < K_MAX) sh[tid] = 0;
    __syncthreads();
    int i = blockIdx.x * 256 + tid;
    if (i < m && i < M_CAP) {
        int cv = d_is64 ? (int)((const long long*)Y)[i] : ((const int*)Y)[i];
        if (cv < 0 || cv >= K_MAX) cv = 0;
        d_cls[i] = cv;
        atomicAdd(&sh[cv], 1);
    }
    __syncthreads();
    if (tid < K_MAX) d_bh[blockIdx.x][tid] = sh[tid];
}

// ------- scan: per-bin exclusive offsets over chunks + class starts --------
__global__ void k_scan(int nchunk) {
    int t = threadIdx.x;
    __shared__ int tot[K_MAX];
    if (t < K_MAX) {
        int run = 0;
        for (int b = 0; b < nchunk; b++) {
            d_boff[b][t] = run;
            run += d_bh[b][t];
        }
        tot[t] = run;
        d_cnt[t] = run;
    }
    __syncthreads();
    if (t == 0) {
        int run = 0;
        for (int c = 0; c < K_MAX; c++) {
            d_cstart[c] = run;
            run += tot[c];
        }
    }
}

// ------- scatter: stable rank within chunk, write sorted index -------------
__global__ void k_scatter(int m) {
    __shared__ int sc[256];
    int tid = threadIdx.x;
    int i = blockIdx.x * 256 + tid;
    sc[tid] = (i < m) ? d_cls[i] : -1;
    __syncthreads();
    if (i < m) {
        int c = sc[tid];
        int rank = 0;
        for (int j = 0; j < tid; j++) rank += (sc[j] == c) ? 1 : 0;
        d_idx[d_cstart[c] + d_boff[blockIdx.x][c] + rank] = i;
    }
}

// ------- per-class Gram: dense gather over sorted class range --------------
__global__ __launch_bounds__(256) void k_gram(const float* __restrict__ X,
                                              int p) {
    int c = blockIdx.y;
    if (c >= d_kval) return;
    int tile = blockIdx.x;
    int ti = 0;
    while ((ti + 1) * (ti + 2) / 2 <= tile) ti++;
    int tj = tile - ti * (ti + 1) / 2;
    int a0 = ti * 128, b0 = tj * 128;
    int z = blockIdx.z;
    int cstart = d_cstart[c], ccnt = d_cnt[c];
    int sb = (int)((long long)ccnt * z / NSLICE);
    int se = (int)((long long)ccnt * (z + 1) / NSLICE);

    __shared__ __align__(16) float sA[32][132];
    __shared__ __align__(16) float sB[32][132];
    __shared__ int sidx[32];

    int tid = threadIdx.x;
    int tx = tid & 15, ty = tid >> 4;
    int lt = tid >> 3, lc = tid & 7;

    ull acc2[8][4];
#pragma unroll
    for (int i = 0; i < 8; i++)
#pragma unroll
        for (int q = 0; q < 4; q++) acc2[i][q] = 0ull;

    for (int base = sb; base < se; base += 32) {
        int nv = se - base;
        if (nv > 32) nv = 32;
        __syncthreads();
        if (tid < 32)
            sidx[tid] = (tid < nv) ? d_idx[cstart + base + tid] : -1;
        __syncthreads();
        {
            int s = sidx[lt];
            if (s >= 0) {
                const float* xr = X + (size_t)s * p;
#pragma unroll
                for (int q = 0; q < 4; q++) {
                    int col = lc * 16 + q * 4;
                    *(float4*)&sA[lt][col] = *(const float4*)&xr[a0 + col];
                    *(float4*)&sB[lt][col] = *(const float4*)&xr[b0 + col];
                }
            }
        }
        __syncthreads();

        for (int t = 0; t < nv; t++) {
            float a[8];
            ull ad[8], b2[4];
            *(float4*)&a[0] = *(const float4*)&sA[t][ty * 8];
            *(float4*)&a[4] = *(const float4*)&sA[t][ty * 8 + 4];
#pragma unroll
            for (int i = 0; i < 8; i++) ad[i] = dup2(a[i]);
#pragma unroll
            for (int q = 0; q < 4; q++)
                b2[q] = *(const ull*)&sB[t][tx * 2 + q * 32];
#pragma unroll
            for (int i = 0; i < 8; i++)
#pragma unroll
                for (int q = 0; q < 4; q++)
                    acc2[i][q] = ffma2(ad[i], b2[q], acc2[i][q]);
        }
    }

    float* G = d_Gk[z][c];
    int gi = a0 + ty * 8;
#pragma unroll
    for (int i = 0; i < 8; i++)
#pragma unroll
        for (int q = 0; q < 4; q++) {
            float2 v = unpk2(acc2[i][q]);
            int col = b0 + q * 32 + tx * 2;
            *(float2*)&G[(size_t)(gi + i) * P + col] = v;
        }
    if (ti != tj) {
#pragma unroll
        for (int i = 0; i < 8; i++)
#pragma unroll
            for (int q = 0; q < 4; q++) {
                float2 v = unpk2(acc2[i][q]);
                int col = b0 + q * 32 + tx * 2;
                G[(size_t)col * P + gi + i]       = v.x;
                G[(size_t)(col + 1) * P + gi + i] = v.y;
            }
    }
}

// --------- assemble A_j = I + scal_j*(sum slices), A_kv = I + scalar*G -----
__global__ __launch_bounds__(256) void k_assemble(int m, float pf) {
    int idx4 = blockIdx.x * blockDim.x + threadIdx.x;
    if (idx4 >= P * P / 4) return;
    int idx = idx4 * 4;
    int r = idx >> 9, c0 = idx & 511;
    int kv = d_kval;
    float dg[4];
#pragma unroll
    for (int q = 0; q < 4; q++) dg[q] = (r == c0 + q) ? 1.f : 0.f;
    float sum[4] = {0.f, 0.f, 0.f, 0.f};
    for (int j = 0; j < kv; j++) {
        float4 g0 = *(const float4*)&d_Gk[0][j][idx];
        float4 g1 = *(const float4*)&d_Gk[1][j][idx];
        float4 g2 = *(const float4*)&d_Gk[2][j][idx];
        float g[4];
        g[0] = g0.x + g1.x + g2.x; g[1] = g0.y + g1.y + g2.y;
        g[2] = g0.z + g1.z + g2.z; g[3] = g0.w + g1.w + g2.w;
        float scal = pf / (((float)d_cnt[j] + 1e-8f) * 0.01f);
        float4 o;
        o.x = dg[0] + scal * g[0]; o.y = dg[1] + scal * g[1];
        o.z = dg[2] + scal * g[2]; o.w = dg[3] + scal * g[3];
        *(float4*)&d_A[j][idx] = o;
#pragma unroll
        for (int q = 0; q < 4; q++) sum[q] += g[q];
    }
    float scalar = pf / ((float)m * 0.01f);
    float4 o;
    o.x = dg[0] + scalar * sum[0]; o.y = dg[1] + scalar * sum[1];
    o.z = dg[2] + scalar * sum[2]; o.w = dg[3] + scalar * sum[3];
    *(float4*)&d_A[kv][idx] = o;
}

// ---- k_diag: rank-8 factor, logdet, Z=L^-1, Dinv=Z^T Z --------------------
__global__ __launch_bounds__(256) void k_diag(int s) {
    int mb = blockIdx.x;
    if (mb > d_kval) return;
    float* A = d_A[mb];
    int sc = s * NB;

    __shared__ float sD[NB * 65];
    __shared__ float sZ[NB * 65];
    __shared__ float sW[8 * 64];
    __shared__ float sdinv[NB];
    __shared__ float sRed[NB];
    int tid = threadIdx.x;
    bool needZ = (s < NSTEP - 1);

    for (int l = tid; l < NB * NB; l += 256) {
        int r = l >> 6, c = l & 63;
        sD[r * 65 + c] = A[(size_t)(sc + r) * P + sc + c];
    }
    if (needZ)
        for (int l = tid; l < NB * 65; l += 256) sZ[l] = 0.f;
    __syncthreads();

#pragma unroll 1
    for (int b = 0; b < NB; b += 8) {
        if (tid < 32) {
#pragma unroll
            for (int t = 0; t < 8; t++) {
                int tt = b + t;
                if (tid == 0) sD[tt * 65 + tt] = sqrtf(sD[tt * 65 + tt]);
                __syncwarp();
                float dinv = 1.f / sD[tt * 65 + tt];
                if (tid > t && tid < 8)
                    sD[(b + tid) * 65 + tt] *= dinv;
                __syncwarp();
                int i = tid >> 2, u = tid & 3;
#pragma unroll
                for (int pass = 0; pass < 2; pass++) {
                    int uu = u + pass * 4;
                    if (uu > t && i >= uu)
                        sD[(b + i) * 65 + b + uu] =
                            fmaf(-sD[(b + i) * 65 + tt],
                                 sD[(b + uu) * 65 + tt],
                                 sD[(b + i) * 65 + b + uu]);
                }
                __syncwarp();
            }
        }
        __syncthreads();

        int rows = NB - b - 8;
        if (rows > 0) {
            if (tid < rows) {
                int r = b + 8 + tid;
                float x[8];
#pragma unroll
                for (int t = 0; t < 8; t++) x[t] = sD[r * 65 + b + t];
#pragma unroll
                for (int t = 0; t < 8; t++) {
                    float v = x[t];
#pragma unroll
                    for (int u = 0; u < t; u++)
                        v = fmaf(-x[u], sD[(b + t) * 65 + b + u], v);
                    x[t] = v / sD[(b + t) * 65 + b + t];
                }
#pragma unroll
                for (int t = 0; t < 8; t++) sD[r * 65 + b + t] = x[t];
            }
            __syncthreads();

            for (int l = tid; l < rows * rows; l += 256) {
                int i = b + 8 + l / rows, u = b + 8 + l % rows;
                float acc = sD[i * 65 + u];
#pragma unroll
                for (int t = 0; t < 8; t++)
                    acc = fmaf(-sD[i * 65 + b + t], sD[u * 65 + b + t], acc);
                sD[i * 65 + u] = acc;
            }
        }
        __syncthreads();
    }

    if (tid < NB) {
        float dv = sD[tid * 65 + tid];
        sRed[tid] = logf(dv);
        sdinv[tid] = 1.f / dv;
    }
    __syncthreads();
    if (tid == 0) {
        double acc = 0.0;
        for (int t = 0; t < NB; t++) acc += (double)sRed[t];
        d_hldd[mb] += acc;
    }
    if (!needZ) return;

    for (int b = 0; b < NB; b += 8) {
        {
            int t0 = tid >> 6;
            int j = tid & 63;
#pragma unroll
            for (int pass = 0; pass < 2; pass++) {
                int t = t0 + pass * 4;
                float acc = 0.f;
                for (int u = 0; u < b; u++)
                    acc = fmaf(sD[(b + t) * 65 + u], sZ[u * 65 + j], acc);
                sW[t * 64 + j] = acc;
            }
        }
        __syncthreads();
        if (tid < 64) {
            int j = tid;
#pragma unroll
            for (int t = 0; t < 8; t++) {
                int r = b + t;
                if (j <= r) {
                    float v = ((r == j) ? 1.f : 0.f) - sW[t * 64 + j];
#pragma unroll
                    for (int u = 0; u < 8; u++) {
                        if (u < t)
                            v = fmaf(-sD[r * 65 + b + u], sZ[(b + u) * 65 + j],
                                     v);
                    }
                    sZ[r * 65 + j] = v * sdinv[r];
                }
            }
        }
        __syncthreads();
    }

    float* DI = d_Dinv[mb];
    for (int l = tid; l < NB * NB; l += 256) {
        int t = l >> 6, u = l & 63;
        int w0 = t > u ? t : u;
        float acc = 0.f;
        for (int w = w0; w < NB; w++)
            acc = fmaf(sZ[w * 65 + t], sZ[w * 65 + u], acc);
        DI[t * DP + u] = acc;
    }
}

// ---- k_ftrail: C_ij -= A_i * Dinv * A_j^T (f32x2 GEMMs) -------------------
__global__ __launch_bounds__(256) void k_ftrail(int s) {
    int mb = blockIdx.y;
    if (mb > d_kval) return;
    int sc = s * NB;
    int l = blockIdx.x;
    int ti = 0;
    while ((ti + 1) * (ti + 2) / 2 <= l) ti++;
    int tj = l - ti * (ti + 1) / 2;
    int ri = sc + NB + ti * NB, rj = sc + NB + tj * NB;
    float* A = d_A[mb];

    extern __shared__ float fs[];
    float* sDv  = fs;
    float* sAjT = fs + NB * DP;
    float* sAiT = fs + 2 * NB * DP;
    float* sT   = fs + 3 * NB * DP;

    int tid = threadIdx.x;

    {
        const float* DI = d_Dinv[mb];
        for (int q = tid; q < NB * DP / 4; q += 256)
            *(float4*)&sDv[q * 4] = *(const float4*)&DI[q * 4];
    }
    {
        int j = tid >> 2, u0 = (tid & 3) * 16;
        const float* rowj = &A[(size_t)(rj + j) * P + sc];
        const float* rowi = &A[(size_t)(ri + j) * P + sc];
#pragma unroll
        for (int q4 = 0; q4 < 4; q4++) {
            float4 vj = *(const float4*)&rowj[u0 + q4 * 4];
            float4 vi = *(const float4*)&rowi[u0 + q4 * 4];
            int u = u0 + q4 * 4;
            sAjT[(u + 0) * DP + j] = vj.x; sAjT[(u + 1) * DP + j] = vj.y;
            sAjT[(u + 2) * DP + j] = vj.z; sAjT[(u + 3) * DP + j] = vj.w;
            sAiT[(u + 0) * DP + j] = vi.x; sAiT[(u + 1) * DP + j] = vi.y;
            sAiT[(u + 2) * DP + j] = vi.z; sAiT[(u + 3) * DP + j] = vi.w;
        }
    }
    __syncthreads();

    int tx = tid & 15, ty = tid >> 4;

    {
        ull acc2[4][2];
#pragma unroll
        for (int i = 0; i < 4; i++) { acc2[i][0] = 0ull; acc2[i][1] = 0ull; }
#pragma unroll 8
        for (int u = 0; u < NB; u++) {
            float4 av = *(const float4*)&sDv[u * DP + ty * 4];
            float4 bv = *(const float4*)&sAjT[u * DP + tx * 4];
            ull b0 = pack2(bv.x, bv.y), b1 = pack2(bv.z, bv.w);
            ull a0 = dup2(av.x), a1 = dup2(av.y);
            ull a2 = dup2(av.z), a3 = dup2(av.w);
            acc2[0][0] = ffma2(a0, b0, acc2[0][0]);
            acc2[0][1] = ffma2(a0, b1, acc2[0][1]);
            acc2[1][0] = ffma2(a1, b0, acc2[1][0]);
            acc2[1][1] = ffma2(a1, b1, acc2[1][1]);
            acc2[2][0] = ffma2(a2, b0, acc2[2][0]);
            acc2[2][1] = ffma2(a2, b1, acc2[2][1]);
            acc2[3][0] = ffma2(a3, b0, acc2[3][0]);
            acc2[3][1] = ffma2(a3, b1, acc2[3][1]);
        }
#pragma unroll
        for (int i = 0; i < 4; i++) {
            float2 lo = unpk2(acc2[i][0]), hi = unpk2(acc2[i][1]);
            float4 v; v.x = lo.x; v.y = lo.y; v.z = hi.x; v.w = hi.y;
            *(float4*)&sT[(ty * 4 + i) * DP + tx * 4] = v;
        }
    }
    __syncthreads();

    {
        ull acc2[4][2];
#pragma unroll
        for (int i = 0; i < 4; i++) { acc2[i][0] = 0ull; acc2[i][1] = 0ull; }
#pragma unroll 8
        for (int t = 0; t < NB; t++) {
            float4 av = *(const float4*)&sAiT[t * DP + ty * 4];
            float4 bv = *(const float4*)&sT[t * DP + tx * 4];
            ull b0 = pack2(bv.x, bv.y), b1 = pack2(bv.z, bv.w);
            ull a0 = dup2(av.x), a1 = dup2(av.y);
            ull a2 = dup2(av.z), a3 = dup2(av.w);
            acc2[0][0] = ffma2(a0, b0, acc2[0][0]);
            acc2[0][1] = ffma2(a0, b1, acc2[0][1]);
            acc2[1][0] = ffma2(a1, b0, acc2[1][0]);
            acc2[1][1] = ffma2(a1, b1, acc2[1][1]);
            acc2[2][0] = ffma2(a2, b0, acc2[2][0]);
            acc2[2][1] = ffma2(a2, b1, acc2[2][1]);
            acc2[3][0] = ffma2(a3, b0, acc2[3][0]);
            acc2[3][1] = ffma2(a3, b1, acc2[3][1]);
        }
#pragma unroll
        for (int q = 0; q < 4; q++) {
            float2 lo = unpk2(acc2[q][0]), hi = unpk2(acc2[q][1]);
            float* row = &A[(size_t)(ri + ty * 4 + q) * P + rj + tx * 4];
            float4 v = *(float4*)row;
            v.x -= lo.x; v.y -= lo.y; v.z -= hi.x; v.w -= hi.y;
            *(float4*)row = v;
        }
    }
}

// ---------------- finalize: two scalars ------------------------------------
__global__ void k_final(float* out, int m) {
    if (threadIdx.x != 0) return;
    int kv = d_kval;
    double comp = 0.0;
    for (int j = 0; j < kv; j++) {
        double trPi = (double)d_cnt[j] + 1e-8;
        comp += d_hldd[j] * trPi / (double)m;
    }
    out[0] = (float)d_hldd[kv];
    out[1] = (float)comp;
}

// ---------------- launch ----------------------------------------------------
extern "C" void kernel_launch(void* const* d_in, const int* in_sizes, int n_in,
                              void* d_out, int out_size) {
    const float* X    = (const float*)d_in[0];
    const void*  Y    = d_in[1];
    const int*   ncls = (n_in >= 3) ? (const int*)d_in[2] : nullptr;
    int m = in_sizes[1];
    int p = in_sizes[0] / m;          // 512
    float* out = (float*)d_out;
    (void)out_size;
    int nchunk = (m + 255) / 256;

    cudaFuncSetAttribute(k_ftrail, cudaFuncAttributeMaxDynamicSharedMemorySize,
                         FT_SMEM_BYTES);

    k_init<<<1, 256>>>(ncls, (const int*)Y);
    k_prep<<<nchunk, 256>>>(Y, m);
    k_scan<<<1, 32>>>(nchunk);
    k_scatter<<<nchunk, 256>>>(m);
    k_gram<<<dim3(10, K_MAX, NSLICE), 256>>>(X, p);
    k_assemble<<<(P * P / 4 + 255) / 256, 256>>>(m, (float)p);
    for (int s = 0; s < NSTEP; s++) {
        k_diag<<<NM, 256>>>(s);
        int nblk = NSTEP - 1 - s;
        if (nblk > 0)
            k_ftrail<<<dim3(nblk * (nblk + 1) / 2, NM), 256,
                       FT_SMEM_BYTES>>>(s);
    }
    k_final<<<1, 32>>>(out, m);
}

// round 8
// speedup vs baseline: 3.1358x; 1.1073x over previous
#include <cuda_runtime.h>
#include <math.h>

#define P       512
#define K_MAX   16
#define NM      (K_MAX + 1)
#define M_CAP   65536
#define NCH_MAX 256
#define NB      64
#define NSTEP   (P / NB)      // 8
#define NSLICE  3
#define DP      68

#define FT_SMEM_BYTES (4 * NB * DP * 4)   // 69632 B

typedef unsigned long long ull;

// ---------------- f32x2 packed helpers (Blackwell sm_103a) -----------------
__device__ __forceinline__ ull ffma2(ull a, ull b, ull c) {
    ull d;
    asm("fma.rn.f32x2 %0, %1, %2, %3;" : "=l"(d) : "l"(a), "l"(b), "l"(c));
    return d;
}
__device__ __forceinline__ ull dup2(float x) {
    ull r; unsigned xb = __float_as_uint(x);
    asm("mov.b64 %0, {%1, %2};" : "=l"(r) : "r"(xb), "r"(xb));
    return r;
}
__device__ __forceinline__ ull pack2(float lo, float hi) {
    ull r;
    asm("mov.b64 %0, {%1, %2};" : "=l"(r) : "f"(lo), "f"(hi));
    return r;
}
__device__ __forceinline__ float2 unpk2(ull v) {
    float2 r;
    asm("mov.b64 {%0, %1}, %2;" : "=f"(r.x), "=f"(r.y) : "l"(v));
    return r;
}

// ---------------- device scratch -------------------------------------------
__device__ int    d_cnt[K_MAX];
__device__ int    d_kval;
__device__ int    d_is64;
__device__ int    d_cls[M_CAP];
__device__ int    d_idx[M_CAP];
__device__ int    d_bh[NCH_MAX][K_MAX];
__device__ int    d_boff[NCH_MAX][K_MAX];
__device__ int    d_cstart[K_MAX];
__device__ float  d_Gk[NSLICE][K_MAX][P * P];
__device__ float  d_A[NM][P * P];
__device__ float  d_Dinv[2][NM][NB * DP];   // double-buffered by step parity
__device__ double d_hldd[NM];

// ------- init ---------------------------------------------------------------
__global__ void k_init(const int* ncls, const int* yw) {
    __shared__ int nz;
    int t = threadIdx.x;
    if (t == 0) nz = 0;
    __syncthreads();
    int found = 0;
    for (int i = t; i < 512; i += blockDim.x)
        if (yw[2 * i + 1] != 0) found = 1;
    if (__any_sync(0xffffffffu, found)) {
        if ((t & 31) == 0) atomicOr(&nz, 1);
    }
    __syncthreads();
    if (t < NM) d_hldd[t] = 0.0;
    if (t == 0) {
        d_is64 = nz ? 0 : 1;
        int k = ncls ? *ncls : 10;
        if (k < 1) k = 1;
        if (k > K_MAX) k = K_MAX;
        d_kval = k;
    }
}

// ------- prep: labels -> int32, per-chunk histogram ------------------------
__global__ void k_prep(const void* __restrict__ Y, int m) {
    __shared__ int sh[K_MAX];
    int tid = threadIdx.x;
    if (tid < K_MAX) sh[tid] = 0;
    __syncthreads();
    int i = blockIdx.x * 256 + tid;
    if (i < m && i < M_CAP) {
        int cv = d_is64 ? (int)((const long long*)Y)[i] : ((const int*)Y)[i];
        if (cv < 0 || cv >= K_MAX) cv = 0;
        d_cls[i] = cv;
        atomicAdd(&sh[cv], 1);
    }
    __syncthreads();
    if (tid < K_MAX) d_bh[blockIdx.x][tid] = sh[tid];
}

// ------- scan ---------------------------------------------------------------
__global__ void k_scan(int nchunk) {
    int t = threadIdx.x;
    __shared__ int tot[K_MAX];
    if (t < K_MAX) {
        int run = 0;
        for (int b = 0; b < nchunk; b++) {
            d_boff[b][t] = run;
            run += d_bh[b][t];
        }
        tot[t] = run;
        d_cnt[t] = run;
    }
    __syncthreads();
    if (t == 0) {
        int run = 0;
        for (int c = 0; c < K_MAX; c++) {
            d_cstart[c] = run;
            run += tot[c];
        }
    }
}

// ------- scatter ------------------------------------------------------------
__global__ void k_scatter(int m) {
    __shared__ int sc[256];
    int tid = threadIdx.x;
    int i = blockIdx.x * 256 + tid;
    sc[tid] = (i < m) ? d_cls[i] : -1;
    __syncthreads();
    if (i < m) {
        int c = sc[tid];
        int rank = 0;
        for (int j = 0; j < tid; j++) rank += (sc[j] == c) ? 1 : 0;
        d_idx[d_cstart[c] + d_boff[blockIdx.x][c] + rank] = i;
    }
}

// ------- per-class Gram: dense gather over sorted class range --------------
__global__ __launch_bounds__(256) void k_gram(const float* __restrict__ X,
                                              int p) {
    int c = blockIdx.y;
    if (c >= d_kval) return;
    int tile = blockIdx.x;
    int ti = 0;
    while ((ti + 1) * (ti + 2) / 2 <= tile) ti++;
    int tj = tile - ti * (ti + 1) / 2;
    int a0 = ti * 128, b0 = tj * 128;
    int z = blockIdx.z;
    int cstart = d_cstart[c], ccnt = d_cnt[c];
    int sb = (int)((long long)ccnt * z / NSLICE);
    int se = (int)((long long)ccnt * (z + 1) / NSLICE);

    __shared__ __align__(16) float sA[32][132];
    __shared__ __align__(16) float sB[32][132];
    __shared__ int sidx[32];

    int tid = threadIdx.x;
    int tx = tid & 15, ty = tid >> 4;
    int lt = tid >> 3, lc = tid & 7;

    ull acc2[8][4];
#pragma unroll
    for (int i = 0; i < 8; i++)
#pragma unroll
        for (int q = 0; q < 4; q++) acc2[i][q] = 0ull;

    for (int base = sb; base < se; base += 32) {
        int nv = se - base;
        if (nv > 32) nv = 32;
        __syncthreads();
        if (tid < 32)
            sidx[tid] = (tid < nv) ? d_idx[cstart + base + tid] : -1;
        __syncthreads();
        {
            int s = sidx[lt];
            if (s >= 0) {
                const float* xr = X + (size_t)s * p;
#pragma unroll
                for (int q = 0; q < 4; q++) {
                    int col = lc * 16 + q * 4;
                    *(float4*)&sA[lt][col] = *(const float4*)&xr[a0 + col];
                    *(float4*)&sB[lt][col] = *(const float4*)&xr[b0 + col];
                }
            }
        }
        __syncthreads();

        for (int t = 0; t < nv; t++) {
            float a[8];
            ull ad[8], b2[4];
            *(float4*)&a[0] = *(const float4*)&sA[t][ty * 8];
            *(float4*)&a[4] = *(const float4*)&sA[t][ty * 8 + 4];
#pragma unroll
            for (int i = 0; i < 8; i++) ad[i] = dup2(a[i]);
#pragma unroll
            for (int q = 0; q < 4; q++)
                b2[q] = *(const ull*)&sB[t][tx * 2 + q * 32];
#pragma unroll
            for (int i = 0; i < 8; i++)
#pragma unroll
                for (int q = 0; q < 4; q++)
                    acc2[i][q] = ffma2(ad[i], b2[q], acc2[i][q]);
        }
    }

    float* G = d_Gk[z][c];
    int gi = a0 + ty * 8;
#pragma unroll
    for (int i = 0; i < 8; i++)
#pragma unroll
        for (int q = 0; q < 4; q++) {
            float2 v = unpk2(acc2[i][q]);
            int col = b0 + q * 32 + tx * 2;
            *(float2*)&G[(size_t)(gi + i) * P + col] = v;
        }
    if (ti != tj) {
#pragma unroll
        for (int i = 0; i < 8; i++)
#pragma unroll
            for (int q = 0; q < 4; q++) {
                float2 v = unpk2(acc2[i][q]);
                int col = b0 + q * 32 + tx * 2;
                G[(size_t)col * P + gi + i]       = v.x;
                G[(size_t)(col + 1) * P + gi + i] = v.y;
            }
    }
}

// --------- assemble ---------------------------------------------------------
__global__ __launch_bounds__(256) void k_assemble(int m, float pf) {
    int idx4 = blockIdx.x * blockDim.x + threadIdx.x;
    if (idx4 >= P * P / 4) return;
    int idx = idx4 * 4;
    int r = idx >> 9, c0 = idx & 511;
    int kv = d_kval;
    float dg[4];
#pragma unroll
    for (int q = 0; q < 4; q++) dg[q] = (r == c0 + q) ? 1.f : 0.f;
    float sum[4] = {0.f, 0.f, 0.f, 0.f};
    for (int j = 0; j < kv; j++) {
        float4 g0 = *(const float4*)&d_Gk[0][j][idx];
        float4 g1 = *(const float4*)&d_Gk[1][j][idx];
        float4 g2 = *(const float4*)&d_Gk[2][j][idx];
        float g[4];
        g[0] = g0.x + g1.x + g2.x; g[1] = g0.y + g1.y + g2.y;
        g[2] = g0.z + g1.z + g2.z; g[3] = g0.w + g1.w + g2.w;
        float scal = pf / (((float)d_cnt[j] + 1e-8f) * 0.01f);
        float4 o;
        o.x = dg[0] + scal * g[0]; o.y = dg[1] + scal * g[1];
        o.z = dg[2] + scal * g[2]; o.w = dg[3] + scal * g[3];
        *(float4*)&d_A[j][idx] = o;
#pragma unroll
        for (int q = 0; q < 4; q++) sum[q] += g[q];
    }
    float scalar = pf / ((float)m * 0.01f);
    float4 o;
    o.x = dg[0] + scalar * sum[0]; o.y = dg[1] + scalar * sum[1];
    o.z = dg[2] + scalar * sum[2]; o.w = dg[3] + scalar * sum[3];
    *(float4*)&d_A[kv][idx] = o;
}

// ---- diag core: factor 64x64 in sD, logdet, Z=L^-1, Dinv -> parity buf ----
__device__ void diag_core(int mb, int s, int tid, float* sD, float* sZ,
                          float* sW, float* sdinv, float* sRed) {
    bool needZ = (s < NSTEP - 1);
    if (needZ)
        for (int l = tid; l < NB * 65; l += 256) sZ[l] = 0.f;
    __syncthreads();

#pragma unroll 1
    for (int b = 0; b < NB; b += 8) {
        if (tid < 32) {
#pragma unroll
            for (int t = 0; t < 8; t++) {
                int tt = b + t;
                if (tid == 0) {
                    float dv = sqrtf(sD[tt * 65 + tt]);
                    sD[tt * 65 + tt] = dv;
                    sdinv[tt] = 1.f / dv;
                }
                __syncwarp();
                float dinv = sdinv[tt];
                if (tid > t && tid < 8)
                    sD[(b + tid) * 65 + tt] *= dinv;
                __syncwarp();
                int i = tid >> 2, u = tid & 3;
#pragma unroll
                for (int pass = 0; pass < 2; pass++) {
                    int uu = u + pass * 4;
                    if (uu > t && i >= uu)
                        sD[(b + i) * 65 + b + uu] =
                            fmaf(-sD[(b + i) * 65 + tt],
                                 sD[(b + uu) * 65 + tt],
                                 sD[(b + i) * 65 + b + uu]);
                }
                __syncwarp();
            }
        }
        __syncthreads();

        int rows = NB - b - 8;
        if (rows > 0) {
            if (tid < rows) {
                int r = b + 8 + tid;
                float x[8];
#pragma unroll
                for (int t = 0; t < 8; t++) x[t] = sD[r * 65 + b + t];
#pragma unroll
                for (int t = 0; t < 8; t++) {
                    float v = x[t];
#pragma unroll
                    for (int u = 0; u < t; u++)
                        v = fmaf(-x[u], sD[(b + t) * 65 + b + u], v);
                    x[t] = v * sdinv[b + t];
                }
#pragma unroll
                for (int t = 0; t < 8; t++) sD[r * 65 + b + t] = x[t];
            }
            __syncthreads();

            for (int l = tid; l < rows * rows; l += 256) {
                int i = b + 8 + l / rows, u = b + 8 + l % rows;
                float acc = sD[i * 65 + u];
#pragma unroll
                for (int t = 0; t < 8; t++)
                    acc = fmaf(-sD[i * 65 + b + t], sD[u * 65 + b + t], acc);
                sD[i * 65 + u] = acc;
            }
        }
        __syncthreads();
    }

    if (tid < NB) sRed[tid] = logf(sD[tid * 65 + tid]);
    __syncthreads();
    if (tid == 0) {
        double acc = 0.0;
        for (int t = 0; t < NB; t++) acc += (double)sRed[t];
        d_hldd[mb] += acc;
    }
    if (!needZ) return;

    // Z = L^{-1}: rank-8 panels
    for (int b = 0; b < NB; b += 8) {
        {
            int t0 = tid >> 6;
            int j = tid & 63;
#pragma unroll
            for (int pass = 0; pass < 2; pass++) {
                int t = t0 + pass * 4;
                float acc = 0.f;
                for (int u = 0; u < b; u++)
                    acc = fmaf(sD[(b + t) * 65 + u], sZ[u * 65 + j], acc);
                sW[t * 64 + j] = acc;
            }
        }
        __syncthreads();
        if (tid < 64) {
            int j = tid;
#pragma unroll
            for (int t = 0; t < 8; t++) {
                int r = b + t;
                if (j <= r) {
                    float v = ((r == j) ? 1.f : 0.f) - sW[t * 64 + j];
#pragma unroll
                    for (int u = 0; u < 8; u++) {
                        if (u < t)
                            v = fmaf(-sD[r * 65 + b + u], sZ[(b + u) * 65 + j],
                                     v);
                    }
                    sZ[r * 65 + j] = v * sdinv[r];
                }
            }
        }
        __syncthreads();
    }

    // Dinv = Z^T Z  -> parity buffer s&1
    float* DI = d_Dinv[s & 1][mb];
    for (int l = tid; l < NB * NB; l += 256) {
        int t = l >> 6, u = l & 63;
        int w0 = t > u ? t : u;
        float acc = 0.f;
        for (int w = w0; w < NB; w++)
            acc = fmaf(sZ[w * 65 + t], sZ[w * 65 + u], acc);
        DI[t * DP + u] = acc;
    }
}

// ---- k_diag0: standalone diag for step 0 ----------------------------------
__global__ __launch_bounds__(256) void k_diag0() {
    int mb = blockIdx.x;
    if (mb > d_kval) return;
    __shared__ float sD[NB * 65];
    __shared__ float sZ[NB * 65];
    __shared__ float sW[8 * 64];
    __shared__ float sdinv[NB];
    __shared__ float sRed[NB];
    int tid = threadIdx.x;
    float* A = d_A[mb];
    for (int l = tid; l < NB * NB; l += 256) {
        int r = l >> 6, c = l & 63;
        sD[r * 65 + c] = A[(size_t)r * P + c];
    }
    diag_core(mb, 0, tid, sD, sZ, sW, sdinv, sRed);
}

// ---- k_step: ftrail tiles; tile(0,0) CTA fuses next step's diag -----------
__global__ __launch_bounds__(256) void k_step(int s) {
    int mb = blockIdx.y;
    if (mb > d_kval) return;
    int sc = s * NB;
    int l = blockIdx.x;
    int ti = 0;
    while ((ti + 1) * (ti + 2) / 2 <= l) ti++;
    int tj = l - ti * (ti + 1) / 2;
    int ri = sc + NB + ti * NB, rj = sc + NB + tj * NB;
    float* A = d_A[mb];

    extern __shared__ float fs[];
    float* sDv  = fs;                 // [64][DP]
    float* sAjT = fs + NB * DP;
    float* sAiT = fs + 2 * NB * DP;
    float* sT   = fs + 3 * NB * DP;

    int tid = threadIdx.x;

    {
        const float* DI = d_Dinv[s & 1][mb];
        for (int q = tid; q < NB * DP / 4; q += 256)
            *(float4*)&sDv[q * 4] = *(const float4*)&DI[q * 4];
    }
    {
        int j = tid >> 2, u0 = (tid & 3) * 16;
        const float* rowj = &A[(size_t)(rj + j) * P + sc];
        const float* rowi = &A[(size_t)(ri + j) * P + sc];
#pragma unroll
        for (int q4 = 0; q4 < 4; q4++) {
            float4 vj = *(const float4*)&rowj[u0 + q4 * 4];
            float4 vi = *(const float4*)&rowi[u0 + q4 * 4];
            int u = u0 + q4 * 4;
            sAjT[(u + 0) * DP + j] = vj.x; sAjT[(u + 1) * DP + j] = vj.y;
            sAjT[(u + 2) * DP + j] = vj.z; sAjT[(u + 3) * DP + j] = vj.w;
            sAiT[(u + 0) * DP + j] = vi.x; sAiT[(u + 1) * DP + j] = vi.y;
            sAiT[(u + 2) * DP + j] = vi.z; sAiT[(u + 3) * DP + j] = vi.w;
        }
    }
    __syncthreads();

    int tx = tid & 15, ty = tid >> 4;

    // GEMM1: T[t][j] = sum_u Dinv[t][u] * A_j[j][u]
    {
        ull acc2[4][2];
#pragma unroll
        for (int i = 0; i < 4; i++) { acc2[i][0] = 0ull; acc2[i][1] = 0ull; }
#pragma unroll 8
        for (int u = 0; u < NB; u++) {
            float4 av = *(const float4*)&sDv[u * DP + ty * 4];
            float4 bv = *(const float4*)&sAjT[u * DP + tx * 4];
            ull b0 = pack2(bv.x, bv.y), b1 = pack2(bv.z, bv.w);
            ull a0 = dup2(av.x), a1 = dup2(av.y);
            ull a2 = dup2(av.z), a3 = dup2(av.w);
            acc2[0][0] = ffma2(a0, b0, acc2[0][0]);
            acc2[0][1] = ffma2(a0, b1, acc2[0][1]);
            acc2[1][0] = ffma2(a1, b0, acc2[1][0]);
            acc2[1][1] = ffma2(a1, b1, acc2[1][1]);
            acc2[2][0] = ffma2(a2, b0, acc2[2][0]);
            acc2[2][1] = ffma2(a2, b1, acc2[2][1]);
            acc2[3][0] = ffma2(a3, b0, acc2[3][0]);
            acc2[3][1] = ffma2(a3, b1, acc2[3][1]);
        }
#pragma unroll
        for (int i = 0; i < 4; i++) {
            float2 lo = unpk2(acc2[i][0]), hi = unpk2(acc2[i][1]);
            float4 v; v.x = lo.x; v.y = lo.y; v.z = hi.x; v.w = hi.y;
            *(float4*)&sT[(ty * 4 + i) * DP + tx * 4] = v;
        }
    }
    __syncthreads();

    // GEMM2: C[i][j] = A[i][j] - sum_t A_i[i][t] * T[t][j]
    ull acc2[4][2];
#pragma unroll
    for (int i = 0; i < 4; i++) { acc2[i][0] = 0ull; acc2[i][1] = 0ull; }
#pragma unroll 8
    for (int t = 0; t < NB; t++) {
        float4 av = *(const float4*)&sAiT[t * DP + ty * 4];
        float4 bv = *(const float4*)&sT[t * DP + tx * 4];
        ull b0 = pack2(bv.x, bv.y), b1 = pack2(bv.z, bv.w);
        ull a0 = dup2(av.x), a1 = dup2(av.y);
        ull a2 = dup2(av.z), a3 = dup2(av.w);
        acc2[0][0] = ffma2(a0, b0, acc2[0][0]);
        acc2[0][1] = ffma2(a0, b1, acc2[0][1]);
        acc2[1][0] = ffma2(a1, b0, acc2[1][0]);
        acc2[1][1] = ffma2(a1, b1, acc2[1][1]);
        acc2[2][0] = ffma2(a2, b0, acc2[2][0]);
        acc2[2][1] = ffma2(a2, b1, acc2[2][1]);
        acc2[3][0] = ffma2(a3, b0, acc2[3][0]);
        acc2[3][1] = ffma2(a3, b1, acc2[3][1]);
    }

    if (l != 0) {
        // normal tile: RMW to global
#pragma unroll
        for (int q = 0; q < 4; q++) {
            float2 lo = unpk2(acc2[q][0]), hi = unpk2(acc2[q][1]);
            float* row = &A[(size_t)(ri + ty * 4 + q) * P + rj + tx * 4];
            float4 v = *(float4*)row;
            v.x -= lo.x; v.y -= lo.y; v.z -= hi.x; v.w -= hi.y;
            *(float4*)row = v;
        }
        return;
    }

    // ---- tile(0,0): keep C in smem and run next step's diag ----------------
    // sD aliases sDv/sAjT (free after GEMM1 sync); sZ aliases sAiT (free
    // after the syncthreads below); sT untouched by diag.
    float* sD    = fs;                // 64*65 = 4160
    float* sdinv = fs + 4160;         // 64
    float* sRed  = fs + 4224;         // 64
    float* sW    = fs + 4288;         // 512  (ends 4800 < 2*NB*DP)
    float* sZ    = fs + 2 * NB * DP;  // 4160 (within sAiT's 4352)

    // C = original A - acc, write straight into sD
#pragma unroll
    for (int q = 0; q < 4; q++) {
        float2 lo = unpk2(acc2[q][0]), hi = unpk2(acc2[q][1]);
        const float* row = &A[(size_t)(ri + ty * 4 + q) * P + rj + tx * 4];
        float4 v = *(const float4*)row;
        int rr = ty * 4 + q, cc = tx * 4;
        sD[rr * 65 + cc + 0] = v.x - lo.x;
        sD[rr * 65 + cc + 1] = v.y - lo.y;
        sD[rr * 65 + cc + 2] = v.z - hi.x;
        sD[rr * 65 + cc + 3] = v.w - hi.y;
    }
    __syncthreads();   // all GEMM2 reads of sAiT/sT done; sD fully written

    diag_core(mb, s + 1, tid, sD, sZ, sW, sdinv, sRed);
}

// ---------------- finalize --------------------------------------------------
__global__ void k_final(float* out, int m) {
    if (threadIdx.x != 0) return;
    int kv = d_kval;
    double comp = 0.0;
    for (int j = 0; j < kv; j++) {
        double trPi = (double)d_cnt[j] + 1e-8;
        comp += d_hldd[j] * trPi / (double)m;
    }
    out[0] = (float)d_hldd[kv];
    out[1] = (float)comp;
}

// ---------------- launch ----------------------------------------------------
extern "C" void kernel_launch(void* const* d_in, const int* in_sizes, int n_in,
                              void* d_out, int out_size) {
    const float* X    = (const float*)d_in[0];
    const void*  Y    = d_in[1];
    const int*   ncls = (n_in >= 3) ? (const int*)d_in[2] : nullptr;
    int m = in_sizes[1];
    int p = in_sizes[0] / m;          // 512
    float* out = (float*)d_out;
    (void)out_size;
    int nchunk = (m + 255) / 256;

    cudaFuncSetAttribute(k_step, cudaFuncAttributeMaxDynamicSharedMemorySize,
                         FT_SMEM_BYTES);

    k_init<<<1, 256>>>(ncls, (const int*)Y);
    k_prep<<<nchunk, 256>>>(Y, m);
    k_scan<<<1, 32>>>(nchunk);
    k_scatter<<<nchunk, 256>>>(m);
    k_gram<<<dim3(10, K_MAX, NSLICE), 256>>>(X, p);
    k_assemble<<<(P * P / 4 + 255) / 256, 256>>>(m, (float)p);
    k_diag0<<<NM, 256>>>();
    for (int s = 0; s < NSTEP - 1; s++) {
        int nblk = NSTEP - 1 - s;
        k_step<<<dim3(nblk * (nblk + 1) / 2, NM), 256, FT_SMEM_BYTES>>>(s);
    }
    k_final<<<1, 32>>>(out, m);
}